// round 15
// baseline (speedup 1.0000x reference)
#include <cuda_runtime.h>
#include <cuda_bf16.h>
#include <math_constants.h>
#include <cstdint>

// ---------------------------------------------------------------------------
// Problem constants
// ---------------------------------------------------------------------------
#define T_MAX   8192
#define C_DIM   2048
#define N_HEAD  16
#define N_KVH   4
#define HDIM    128
#define WIN     1024
#define RMS_EPS 1.1920929e-07f

// ---------------------------------------------------------------------------
// Scratch (device globals; no runtime allocation allowed)
// ---------------------------------------------------------------------------
__device__ float g_q[(size_t)T_MAX * 2048];            // x @ Wq (fp32)
__device__ float g_k[(size_t)T_MAX * 512];
__device__ float g_v[(size_t)T_MAX * 512];
// bf16 hi/lo planes
__device__ __nv_bfloat16 g_xh[(size_t)T_MAX * 2048];
__device__ __nv_bfloat16 g_xl[(size_t)T_MAX * 2048];
__device__ __nv_bfloat16 g_yh[(size_t)T_MAX * 2048];
__device__ __nv_bfloat16 g_yl[(size_t)T_MAX * 2048];
__device__ __nv_bfloat16 g_wqh[(size_t)2048 * 2048];
__device__ __nv_bfloat16 g_wql[(size_t)2048 * 2048];
__device__ __nv_bfloat16 g_wph[(size_t)2048 * 2048];
__device__ __nv_bfloat16 g_wpl[(size_t)2048 * 2048];
__device__ __nv_bfloat16 g_Qph[(size_t)N_HEAD * T_MAX * HDIM];
__device__ __nv_bfloat16 g_Qpl[(size_t)N_HEAD * T_MAX * HDIM];
__device__ __nv_bfloat16 g_Kph[(size_t)N_KVH * T_MAX * HDIM];
__device__ __nv_bfloat16 g_Kpl[(size_t)N_KVH * T_MAX * HDIM];
__device__ __nv_bfloat16 g_Vph[(size_t)N_KVH * T_MAX * HDIM];
__device__ __nv_bfloat16 g_Vpl[(size_t)N_KVH * T_MAX * HDIM];

// ---------------------------------------------------------------------------
// PTX helpers
// ---------------------------------------------------------------------------
__device__ __forceinline__ void mma_bf16(float* d,
                                         const uint32_t* a, const uint32_t* b) {
    asm volatile(
        "mma.sync.aligned.m16n8k16.row.col.f32.bf16.bf16.f32 "
        "{%0,%1,%2,%3}, {%4,%5,%6,%7}, {%8,%9}, {%0,%1,%2,%3};"
        : "+f"(d[0]), "+f"(d[1]), "+f"(d[2]), "+f"(d[3])
        : "r"(a[0]), "r"(a[1]), "r"(a[2]), "r"(a[3]),
          "r"(b[0]), "r"(b[1]));
}
__device__ __forceinline__ void ldsm_x4(uint32_t* r, uint32_t saddr) {
    asm volatile(
        "ldmatrix.sync.aligned.m8n8.x4.shared.b16 {%0,%1,%2,%3}, [%4];"
        : "=r"(r[0]), "=r"(r[1]), "=r"(r[2]), "=r"(r[3]) : "r"(saddr));
}
__device__ __forceinline__ void ldsm_x4_trans(uint32_t* r, uint32_t saddr) {
    asm volatile(
        "ldmatrix.sync.aligned.m8n8.x4.trans.shared.b16 {%0,%1,%2,%3}, [%4];"
        : "=r"(r[0]), "=r"(r[1]), "=r"(r[2]), "=r"(r[3]) : "r"(saddr));
}
__device__ __forceinline__ void cp_async16(uint32_t s, const void* g) {
    asm volatile("cp.async.cg.shared.global [%0], [%1], 16;" :: "r"(s), "l"(g));
}
#define CP_COMMIT() asm volatile("cp.async.commit_group;" ::: "memory")
#define CP_WAIT0()  asm volatile("cp.async.wait_group 0;" ::: "memory")
#define CP_WAIT1()  asm volatile("cp.async.wait_group 1;" ::: "memory")

// packed fp32x2 FMA: two independent IEEE-RN fp32 FMAs in one instruction
__device__ __forceinline__ void fma2(unsigned long long& d,
                                     unsigned long long a, unsigned long long b) {
    asm("fma.rn.f32x2 %0, %1, %2, %0;" : "+l"(d) : "l"(a), "l"(b));
}
__device__ __forceinline__ void unpack2(unsigned long long v, float& lo, float& hi) {
    asm("mov.b64 {%0,%1}, %2;" : "=f"(lo), "=f"(hi) : "l"(v));
}

__device__ __forceinline__ uint32_t smem_to_u32(const void* p) {
    uint32_t a;
    asm("{ .reg .u64 t; cvta.to.shared.u64 t, %1; cvt.u32.u64 %0, t; }"
        : "=r"(a) : "l"(p));
    return a;
}
__device__ __forceinline__ uint32_t pack_bf16(__nv_bfloat16 a, __nv_bfloat16 b) {
    return (uint32_t)__bfloat16_as_ushort(a) |
           ((uint32_t)__bfloat16_as_ushort(b) << 16);
}
__device__ __forceinline__ void split2_pack(float x, float y,
                                            uint32_t& hi, uint32_t& lo) {
    __nv_bfloat16 hx = __float2bfloat16(x);
    __nv_bfloat16 hy = __float2bfloat16(y);
    __nv_bfloat16 lx = __float2bfloat16(__fsub_rn(x, __bfloat162float(hx)));
    __nv_bfloat16 ly = __float2bfloat16(__fsub_rn(y, __bfloat162float(hy)));
    hi = pack_bf16(hx, hy);
    lo = pack_bf16(lx, ly);
}
__device__ __forceinline__ void split1(float x, __nv_bfloat16& h, __nv_bfloat16& l) {
    h = __float2bfloat16(x);
    l = __float2bfloat16(__fsub_rn(x, __bfloat162float(h)));
}

// ---------------------------------------------------------------------------
// fp32 -> (hi, lo) bf16 split, elementwise. n4 = n/4.
// ---------------------------------------------------------------------------
__global__ void split_bf16_kernel(const float* __restrict__ X,
                                  __nv_bfloat16* __restrict__ H,
                                  __nv_bfloat16* __restrict__ L, int n4)
{
    int i = blockIdx.x * blockDim.x + threadIdx.x;
    if (i >= n4) return;
    float4 v = ((const float4*)X)[i];
    float xs[4] = {v.x, v.y, v.z, v.w};
    union { __nv_bfloat16 b[4]; uint2 u; } ph, pl;
#pragma unroll
    for (int j = 0; j < 4; j++) split1(xs[j], ph.b[j], pl.b[j]);
    *(uint2*)(H + (size_t)i * 4) = ph.u;
    *(uint2*)(L + (size_t)i * 4) = pl.u;
}

// ---------------------------------------------------------------------------
// W [K, N] fp32 -> Wt hi/lo bf16 [N, K] (transpose + split). 32x32 tiles.
// ---------------------------------------------------------------------------
__global__ void transpose_split_kernel(const float* __restrict__ W,
                                       __nv_bfloat16* __restrict__ Th,
                                       __nv_bfloat16* __restrict__ Tl,
                                       int K, int N)
{
    __shared__ float tile[32][33];
    int k0 = blockIdx.y * 32, n0 = blockIdx.x * 32;
    int tx = threadIdx.x & 31, ty = threadIdx.x >> 5;
#pragma unroll
    for (int r = ty; r < 32; r += 8)
        tile[r][tx] = W[(size_t)(k0 + r) * N + n0 + tx];
    __syncthreads();
#pragma unroll
    for (int r = ty; r < 32; r += 8) {
        __nv_bfloat16 h, l;
        split1(tile[tx][r], h, l);
        Th[(size_t)(n0 + r) * K + k0 + tx] = h;
        Tl[(size_t)(n0 + r) * K + k0 + tx] = l;
    }
}

// ---------------------------------------------------------------------------
// bf16x3 tensor-core GEMM (unchanged from Round 12/13/14).
// ---------------------------------------------------------------------------
#define GST 40
#define GPL (128 * GST * 2)
#define GSTG (4 * GPL)
#define GEMM_SMEM (2 * GSTG)

__global__ __launch_bounds__(256, 2) void gemm_bf16x3_kernel(
    const __nv_bfloat16* __restrict__ Ah, const __nv_bfloat16* __restrict__ Al,
    const __nv_bfloat16* __restrict__ Bh, const __nv_bfloat16* __restrict__ Bl,
    float* __restrict__ C, int M, int N, int K)
{
    extern __shared__ __nv_bfloat16 gsm[];
    const uint32_t sbu = smem_to_u32(gsm);

    const int tid  = threadIdx.x;
    const int lane = tid & 31;
    const int wid  = tid >> 5;
    const int wm   = wid & 1;
    const int wn   = wid >> 1;

    const __nv_bfloat16* gAh = Ah + (size_t)blockIdx.y * 128 * K;
    const __nv_bfloat16* gAl = Al + (size_t)blockIdx.y * 128 * K;
    const __nv_bfloat16* gBh = Bh + (size_t)blockIdx.x * 128 * K;
    const __nv_bfloat16* gBl = Bl + (size_t)blockIdx.x * 128 * K;

    const int srow0 = tid >> 2, sc0 = (tid & 3) * 8;
    const int srow1 = (tid + 256) >> 2, sc1 = ((tid + 256) & 3) * 8;

    float acc[4][4][4];
#pragma unroll
    for (int mt = 0; mt < 4; mt++)
#pragma unroll
        for (int nt = 0; nt < 4; nt++)
#pragma unroll
            for (int e = 0; e < 4; e++) acc[mt][nt][e] = 0.f;

    const uint32_t aRow = (lane & 15);
    const uint32_t aCol = (lane & 16) ? 8 : 0;
    const uint32_t bRow = (lane & 7) + ((lane & 16) >> 1);
    const uint32_t bCol = (lane & 8);

    const int nIter = K / 32;

    {
        uint32_t base = sbu;
        size_t go0 = (size_t)srow0 * K + sc0;
        size_t go1 = (size_t)srow1 * K + sc1;
        uint32_t so0 = base + (srow0 * GST + sc0) * 2;
        uint32_t so1 = base + (srow1 * GST + sc1) * 2;
        cp_async16(so0,           gAh + go0);
        cp_async16(so0 + GPL,     gAl + go0);
        cp_async16(so0 + 2 * GPL, gBh + go0);
        cp_async16(so0 + 3 * GPL, gBl + go0);
        cp_async16(so1,           gAh + go1);
        cp_async16(so1 + GPL,     gAl + go1);
        cp_async16(so1 + 2 * GPL, gBh + go1);
        cp_async16(so1 + 3 * GPL, gBl + go1);
        CP_COMMIT();
    }

    int cur = 0;
    for (int it = 0; it < nIter; it++) {
        CP_WAIT0();
        __syncthreads();

        if (it + 1 < nIter) {
            int k0n = (it + 1) * 32;
            uint32_t base = sbu + (cur ^ 1) * GSTG;
            size_t go0 = (size_t)srow0 * K + k0n + sc0;
            size_t go1 = (size_t)srow1 * K + k0n + sc1;
            uint32_t so0 = base + (srow0 * GST + sc0) * 2;
            uint32_t so1 = base + (srow1 * GST + sc1) * 2;
            cp_async16(so0,           gAh + go0);
            cp_async16(so0 + GPL,     gAl + go0);
            cp_async16(so0 + 2 * GPL, gBh + go0);
            cp_async16(so0 + 3 * GPL, gBl + go0);
            cp_async16(so1,           gAh + go1);
            cp_async16(so1 + GPL,     gAl + go1);
            cp_async16(so1 + 2 * GPL, gBh + go1);
            cp_async16(so1 + 3 * GPL, gBl + go1);
            CP_COMMIT();
        }

        const uint32_t bA = sbu + cur * GSTG;
        const uint32_t bAl_ = bA + GPL;
        const uint32_t bB = bA + 2 * GPL;
        const uint32_t bBl_ = bA + 3 * GPL;

#pragma unroll
        for (int ks = 0; ks < 2; ks++) {
            const int ko = ks * 16;
            uint32_t bh[4][2], bl[4][2];
#pragma unroll
            for (int p = 0; p < 2; p++) {
                uint32_t roff = ((wn * 32 + p * 16 + bRow) * GST + ko + bCol) * 2;
                uint32_t t4[4];
                ldsm_x4(t4, bB + roff);
                bh[2 * p][0] = t4[0]; bh[2 * p][1] = t4[1];
                bh[2 * p + 1][0] = t4[2]; bh[2 * p + 1][1] = t4[3];
                ldsm_x4(t4, bBl_ + roff);
                bl[2 * p][0] = t4[0]; bl[2 * p][1] = t4[1];
                bl[2 * p + 1][0] = t4[2]; bl[2 * p + 1][1] = t4[3];
            }
#pragma unroll
            for (int mt = 0; mt < 4; mt++) {
                uint32_t aoff = ((wm * 64 + mt * 16 + aRow) * GST + ko + aCol) * 2;
                uint32_t ah[4], al[4];
                ldsm_x4(ah, bA + aoff);
                ldsm_x4(al, bAl_ + aoff);
#pragma unroll
                for (int nt = 0; nt < 4; nt++) {
                    mma_bf16(acc[mt][nt], al, bh[nt]);
                    mma_bf16(acc[mt][nt], ah, bl[nt]);
                    mma_bf16(acc[mt][nt], ah, bh[nt]);
                }
            }
        }
        cur ^= 1;
    }

    const int g2 = lane >> 2, tig2 = lane & 3;
#pragma unroll
    for (int mt = 0; mt < 4; mt++) {
#pragma unroll
        for (int nt = 0; nt < 4; nt++) {
            int r = blockIdx.y * 128 + wm * 64 + mt * 16 + g2;
            int c = blockIdx.x * 128 + wn * 32 + nt * 8 + tig2 * 2;
            *(float2*)(C + (size_t)r * N + c) =
                make_float2(acc[mt][nt][0], acc[mt][nt][1]);
            *(float2*)(C + (size_t)(r + 8) * N + c) =
                make_float2(acc[mt][nt][2], acc[mt][nt][3]);
        }
    }
}

// ---------------------------------------------------------------------------
// K/V projection SGEMM — *** ARITHMETIC FROZEN *** (LLVM-interleaved-16:
// part[j] accumulates k ≡ j mod 16 ascending, pairwise fold at end).
// v3: packed fp32x2 FMA (two independent IEEE-RN chains per instruction);
// B staged pre-duplicated (b,b) so the packed broadcast operand is a plain
// LDS.64. Per-lane arithmetic bit-identical to v2.
// ---------------------------------------------------------------------------
#define KVST 36   // A smem row stride (floats)

__global__ __launch_bounds__(256) void sgemm_kv_kernel(
    const float* __restrict__ A, const float* __restrict__ B,
    float* __restrict__ C, int M, int N, int K)
{
    __shared__ float  As[2][32][KVST];   // [buf][k][m]
    __shared__ float2 Bs[2][32][34];     // [buf][k][n], value duplicated (b,b)

    const int tid = threadIdx.x;
    const int tx  = tid & 31;       // n within tile
    const int ty  = tid >> 5;       // row group (4 rows each)
    const int bx  = blockIdx.x;
    const int by  = blockIdx.y;

    const float* Ab = A + (size_t)(by * 32) * K;
    const float* Bb = B + (size_t)(bx * 32);

    const int am = tid >> 3;            // 0..31
    const int ak = (tid & 7) << 2;      // 0,4,...,28
    const int bk = tid >> 3;            // 0..31
    const int bn = (tid & 7) << 2;      // 0,4,...,28

    // packed accumulators: p01[j] = (part[0][j], part[1][j]), p23 likewise
    unsigned long long p01[16], p23[16];
#pragma unroll
    for (int j = 0; j < 16; j++) { p01[j] = 0ull; p23[j] = 0ull; }

    const int nIter = K / 32;
    float4 a_reg = *(const float4*)(Ab + (size_t)am * K + ak);
    float4 b_reg = *(const float4*)(Bb + (size_t)bk * N + bn);

    int buf = 0;
    for (int it = 0; it < nIter; it++) {
        As[buf][ak + 0][am] = a_reg.x;
        As[buf][ak + 1][am] = a_reg.y;
        As[buf][ak + 2][am] = a_reg.z;
        As[buf][ak + 3][am] = a_reg.w;
        Bs[buf][bk][bn + 0] = make_float2(b_reg.x, b_reg.x);
        Bs[buf][bk][bn + 1] = make_float2(b_reg.y, b_reg.y);
        Bs[buf][bk][bn + 2] = make_float2(b_reg.z, b_reg.z);
        Bs[buf][bk][bn + 3] = make_float2(b_reg.w, b_reg.w);
        __syncthreads();

        if (it + 1 < nIter) {
            int k0n = (it + 1) * 32;
            a_reg = *(const float4*)(Ab + (size_t)am * K + k0n + ak);
            b_reg = *(const float4*)(Bb + (size_t)(k0n + bk) * N + bn);
        }

        // per residue j: k0+j then k0+16+j (ascending k within each chain)
#pragma unroll
        for (int j = 0; j < 16; j++) {
            ulonglong2 a0 = *(const ulonglong2*)&As[buf][j][ty * 4];
            unsigned long long b0 = *(const unsigned long long*)&Bs[buf][j][tx];
            fma2(p01[j], a0.x, b0);
            fma2(p23[j], a0.y, b0);
            ulonglong2 a1 = *(const ulonglong2*)&As[buf][j + 16][ty * 4];
            unsigned long long b1 = *(const unsigned long long*)&Bs[buf][j + 16][tx];
            fma2(p01[j], a1.x, b1);
            fma2(p23[j], a1.y, b1);
        }
        buf ^= 1;
    }

    // unpack, then LLVM-style pairwise fold (unchanged arithmetic)
    float part[4][16];
#pragma unroll
    for (int j = 0; j < 16; j++) {
        unpack2(p01[j], part[0][j], part[1][j]);
        unpack2(p23[j], part[2][j], part[3][j]);
    }
#pragma unroll
    for (int r = 0; r < 4; r++) {
        float w[4];
#pragma unroll
        for (int l = 0; l < 4; l++)
            w[l] = __fadd_rn(__fadd_rn(part[r][l],     part[r][4 + l]),
                             __fadd_rn(part[r][8 + l], part[r][12 + l]));
        float res = __fadd_rn(__fadd_rn(w[0], w[1]), __fadd_rn(w[2], w[3]));
        C[(size_t)(by * 32 + ty * 4 + r) * N + bx * 32 + tx] = res;
    }
}

__device__ __forceinline__ float rsqrt_rn(float x) {
    return __fdiv_rn(1.0f, __fsqrt_rn(x));
}

// ---------------------------------------------------------------------------
// RoPE + RMS for Q -> bf16 hi/lo planes.
// ---------------------------------------------------------------------------
__global__ void rope_rms_q_kernel(
    const float* __restrict__ X, const float* __restrict__ cosb,
    const float* __restrict__ sinb,
    __nv_bfloat16* __restrict__ Qh, __nv_bfloat16* __restrict__ Ql, int T)
{
    const int t = blockIdx.x, h = blockIdx.y, d = threadIdx.x;
    const float* row = X + (size_t)t * 2048 + h * 128;
    float x1 = row[d], x2 = row[d + 64];
    float c = cosb[t * 64 + d], s = sinb[t * 64 + d];
    float o1 = __fadd_rn(__fmul_rn(x1, c), __fmul_rn(x2, s));
    float o2 = __fsub_rn(__fmul_rn(x2, c), __fmul_rn(x1, s));

    float ss = __fadd_rn(__fmul_rn(o1, o1), __fmul_rn(o2, o2));
#pragma unroll
    for (int o = 16; o > 0; o >>= 1) ss += __shfl_down_sync(0xffffffffu, ss, o);
    __shared__ float sh[2];
    if ((d & 31) == 0) sh[d >> 5] = ss;
    __syncthreads();
    float ms = __fmul_rn(__fadd_rn(sh[0], sh[1]), 0.0078125f);
    float r = rsqrt_rn(__fadd_rn(ms, RMS_EPS));

    size_t base = ((size_t)h * T + t) * 128;
    __nv_bfloat16 hh, ll;
    split1(__fmul_rn(o1, r), hh, ll);
    Qh[base + d] = hh;  Ql[base + d] = ll;
    split1(__fmul_rn(o2, r), hh, ll);
    Qh[base + d + 64] = hh;  Ql[base + d + 64] = ll;
}

// ---------------------------------------------------------------------------
// RoPE + RMS + quant for K — frozen fp32 chain, then split to planes.
// ---------------------------------------------------------------------------
__global__ void rope_rms_quant_k_kernel(
    const float* __restrict__ X, const float* __restrict__ cosb,
    const float* __restrict__ sinb,
    __nv_bfloat16* __restrict__ Kh, __nv_bfloat16* __restrict__ Kl, int T)
{
    const int t = blockIdx.x, h = blockIdx.y, d = threadIdx.x;
    const float* row = X + (size_t)t * 512 + h * 128;
    float x1 = row[d], x2 = row[d + 64];
    float c = cosb[t * 64 + d], s = sinb[t * 64 + d];
    float o1 = __fadd_rn(__fmul_rn(x1, c), __fmul_rn(x2, s));
    float o2 = __fsub_rn(__fmul_rn(x2, c), __fmul_rn(x1, s));

    __shared__ float sh[4];
    float ss = __fadd_rn(__fmul_rn(o1, o1), __fmul_rn(o2, o2));
#pragma unroll
    for (int o = 16; o > 0; o >>= 1) ss += __shfl_down_sync(0xffffffffu, ss, o);
    if ((d & 31) == 0) sh[d >> 5] = ss;
    __syncthreads();
    float ms = __fmul_rn(__fadd_rn(sh[0], sh[1]), 0.0078125f);
    float r = rsqrt_rn(__fadd_rn(ms, RMS_EPS));
    float k1 = __fmul_rn(o1, r), k2 = __fmul_rn(o2, r);

    float m = fmaxf(fabsf(k1), fabsf(k2));
#pragma unroll
    for (int o = 16; o > 0; o >>= 1) m = fmaxf(m, __shfl_down_sync(0xffffffffu, m, o));
    if ((d & 31) == 0) sh[2 + (d >> 5)] = m;
    __syncthreads();
    float sq = fmaxf(__fdiv_rn(fmaxf(sh[2], sh[3]), 3.0f), 1e-8f);
    float q1 = __fmul_rn(fminf(fmaxf(rintf(__fdiv_rn(k1, sq)), -3.f), 3.f), sq);
    float q2 = __fmul_rn(fminf(fmaxf(rintf(__fdiv_rn(k2, sq)), -3.f), 3.f), sq);

    size_t base = ((size_t)h * T + t) * 128;
    __nv_bfloat16 hh, ll;
    split1(q1, hh, ll);
    Kh[base + d] = hh;  Kl[base + d] = ll;
    split1(q2, hh, ll);
    Kh[base + d + 64] = hh;  Kl[base + d + 64] = ll;
}

// ---------------------------------------------------------------------------
// Quant V — frozen fp32 chain, then split to planes.
// ---------------------------------------------------------------------------
__global__ void quant_v_kernel(
    const float* __restrict__ X,
    __nv_bfloat16* __restrict__ Vh, __nv_bfloat16* __restrict__ Vl, int T)
{
    const int t = blockIdx.x, h = blockIdx.y, d = threadIdx.x;
    const float* row = X + (size_t)t * 512 + h * 128;
    float v1 = row[d], v2 = row[d + 64];

    __shared__ float sh[2];
    float m = fmaxf(fabsf(v1), fabsf(v2));
#pragma unroll
    for (int o = 16; o > 0; o >>= 1) m = fmaxf(m, __shfl_down_sync(0xffffffffu, m, o));
    if ((d & 31) == 0) sh[d >> 5] = m;
    __syncthreads();
    float sq = fmaxf(__fdiv_rn(fmaxf(sh[0], sh[1]), 3.0f), 1e-8f);
    float q1 = __fmul_rn(fminf(fmaxf(rintf(__fdiv_rn(v1, sq)), -3.f), 3.f), sq);
    float q2 = __fmul_rn(fminf(fmaxf(rintf(__fdiv_rn(v2, sq)), -3.f), 3.f), sq);

    size_t base = ((size_t)h * T + t) * 128;
    __nv_bfloat16 hh, ll;
    split1(q1, hh, ll);
    Vh[base + d] = hh;  Vl[base + d] = ll;
    split1(q2, hh, ll);
    Vh[base + d + 64] = hh;  Vl[base + d + 64] = ll;
}

// ---------------------------------------------------------------------------
// Tensor-core flash attention v3 (Round 12 WIN, unchanged).
// ---------------------------------------------------------------------------
#define QST 136
#define QPL (128 * QST * 2)
#define KPL (64 * QST * 2)
#define KVBUF (4 * KPL)
#define ATT_SMEM (2 * QPL + 2 * KVBUF)

__global__ __launch_bounds__(256) void attn_tc_kernel(
    const __nv_bfloat16* __restrict__ Qh, const __nv_bfloat16* __restrict__ Ql,
    const __nv_bfloat16* __restrict__ Kh, const __nv_bfloat16* __restrict__ Kl,
    const __nv_bfloat16* __restrict__ Vh, const __nv_bfloat16* __restrict__ Vl,
    __nv_bfloat16* __restrict__ Yh, __nv_bfloat16* __restrict__ Yl, int T)
{
    extern __shared__ __nv_bfloat16 sm[];
    const uint32_t uQ  = smem_to_u32(sm);
    const uint32_t uQl = uQ + QPL;
    const uint32_t uKV = uQ + 2 * QPL;

    const int tid  = threadIdx.x;
    const int lane = tid & 31;
    const int wr   = tid >> 5;
    const int g    = lane >> 2;
    const int tig  = lane & 3;
    const int h    = blockIdx.y;
    const int t0   = blockIdx.x << 7;
    const int hk   = h >> 2;
    const int r0   = wr * 16;

    const uint32_t aRow = (lane & 15);
    const uint32_t aCol = (lane & 16) ? 8 : 0;
    const uint32_t bRow = (lane & 7) + ((lane & 16) >> 1);
    const uint32_t bCol = (lane & 8);
    const uint32_t vKey = (lane & 7) + ((lane >> 3) & 1) * 8;
    const uint32_t vDim = (lane >> 4) * 8;

    const __nv_bfloat16* gQh = Qh + ((size_t)h * T + t0) * 128;
    const __nv_bfloat16* gQl = Ql + ((size_t)h * T + t0) * 128;
    const __nv_bfloat16* gKh = Kh + (size_t)hk * T * 128;
    const __nv_bfloat16* gKl = Kl + (size_t)hk * T * 128;
    const __nv_bfloat16* gVh = Vh + (size_t)hk * T * 128;
    const __nv_bfloat16* gVl = Vl + (size_t)hk * T * 128;
    const float scale = 0.08838834764831845f;

    int kb0 = t0 - WIN; if (kb0 < 0) kb0 = 0;
    const int kbend = t0 + 64;

#pragma unroll
    for (int i = 0; i < 16; i++) {
        int cidx = tid + 256 * i;
        int plane = cidx >> 11, rem = cidx & 2047;
        int row = rem >> 4, ch = rem & 15;
        const __nv_bfloat16* src = (plane ? gQl : gQh) + (size_t)row * 128 + ch * 8;
        cp_async16(uQ + plane * QPL + (row * QST + ch * 8) * 2, src);
    }
    {
        const __nv_bfloat16* srcs[4] = {gKh, gKl, gVh, gVl};
#pragma unroll
        for (int i = 0; i < 16; i++) {
            int cidx = tid + 256 * i;
            int plane = cidx >> 10, rem = cidx & 1023;
            int row = rem >> 4, ch = rem & 15;
            cp_async16(uKV + plane * KPL + (row * QST + ch * 8) * 2,
                       srcs[plane] + (size_t)(kb0 + row) * 128 + ch * 8);
        }
    }
    CP_COMMIT();

    float m0 = -CUDART_INF_F, m1 = -CUDART_INF_F, l0s = 0.f, l1s = 0.f;
    float oacc[16][4];
#pragma unroll
    for (int nt = 0; nt < 16; nt++)
#pragma unroll
        for (int e = 0; e < 4; e++) oacc[nt][e] = 0.f;

    int cur = 0;
    for (int kb = kb0; kb <= kbend; kb += 64) {
        const bool has_next = (kb + 64 <= kbend);
        if (has_next) {
            const __nv_bfloat16* srcs[4] = {gKh, gKl, gVh, gVl};
            uint32_t dstb = uKV + (cur ^ 1) * KVBUF;
#pragma unroll
            for (int i = 0; i < 16; i++) {
                int cidx = tid + 256 * i;
                int plane = cidx >> 10, rem = cidx & 1023;
                int row = rem >> 4, ch = rem & 15;
                cp_async16(dstb + plane * KPL + (row * QST + ch * 8) * 2,
                           srcs[plane] + (size_t)(kb + 64 + row) * 128 + ch * 8);
            }
            CP_COMMIT();
            CP_WAIT1();
        } else {
            CP_WAIT0();
        }
        __syncthreads();

        const uint32_t uKh_ = uKV + cur * KVBUF;
        const uint32_t uKl_ = uKh_ + KPL;
        const uint32_t uVh_ = uKh_ + 2 * KPL;
        const uint32_t uVl_ = uKh_ + 3 * KPL;

        float sacc[8][4];
#pragma unroll
        for (int nt = 0; nt < 8; nt++)
#pragma unroll
            for (int e = 0; e < 4; e++) sacc[nt][e] = 0.f;

#pragma unroll
        for (int kt = 0; kt < 8; kt++) {
            const int kc = kt * 16;
            uint32_t qoff = ((r0 + aRow) * QST + kc + aCol) * 2;
            uint32_t ah[4], al[4];
            ldsm_x4(ah, uQ + qoff);
            ldsm_x4(al, uQl + qoff);

            uint32_t kfh[8][2], kfl[8][2];
#pragma unroll
            for (int p = 0; p < 4; p++) {
                uint32_t koff = ((p * 16 + bRow) * QST + kc + bCol) * 2;
                uint32_t t4[4];
                ldsm_x4(t4, uKh_ + koff);
                kfh[2 * p][0] = t4[0]; kfh[2 * p][1] = t4[1];
                kfh[2 * p + 1][0] = t4[2]; kfh[2 * p + 1][1] = t4[3];
                ldsm_x4(t4, uKl_ + koff);
                kfl[2 * p][0] = t4[0]; kfl[2 * p][1] = t4[1];
                kfl[2 * p + 1][0] = t4[2]; kfl[2 * p + 1][1] = t4[3];
            }
#pragma unroll
            for (int nt = 0; nt < 8; nt++) {
                mma_bf16(sacc[nt], al, kfh[nt]);
                mma_bf16(sacc[nt], ah, kfl[nt]);
                mma_bf16(sacc[nt], ah, kfh[nt]);
            }
        }

        const int row0 = t0 + r0 + g;
        const int row1 = row0 + 8;
        float rmax0 = -CUDART_INF_F, rmax1 = -CUDART_INF_F;
#pragma unroll
        for (int nt = 0; nt < 8; nt++) {
            int c0 = kb + nt * 8 + tig * 2;
#pragma unroll
            for (int e = 0; e < 4; e++) {
                int col = c0 + (e & 1);
                int row = (e < 2) ? row0 : row1;
                bool valid = (col <= row) && (col + WIN > row);
                float s = valid ? sacc[nt][e] * scale : -CUDART_INF_F;
                sacc[nt][e] = s;
                if (e < 2) rmax0 = fmaxf(rmax0, s);
                else       rmax1 = fmaxf(rmax1, s);
            }
        }
        rmax0 = fmaxf(rmax0, __shfl_xor_sync(0xffffffffu, rmax0, 1));
        rmax0 = fmaxf(rmax0, __shfl_xor_sync(0xffffffffu, rmax0, 2));
        rmax1 = fmaxf(rmax1, __shfl_xor_sync(0xffffffffu, rmax1, 1));
        rmax1 = fmaxf(rmax1, __shfl_xor_sync(0xffffffffu, rmax1, 2));

        float mn0 = fmaxf(m0, rmax0), mn1 = fmaxf(m1, rmax1);
        float mm0 = (mn0 == -CUDART_INF_F) ? 0.f : mn0;
        float mm1 = (mn1 == -CUDART_INF_F) ? 0.f : mn1;
        float c0 = __expf(m0 - mm0);
        float c1 = __expf(m1 - mm1);
        if (m0 == -CUDART_INF_F) c0 = (mn0 == -CUDART_INF_F) ? 1.f : 0.f;
        if (m1 == -CUDART_INF_F) c1 = (mn1 == -CUDART_INF_F) ? 1.f : 0.f;

        float sum0 = 0.f, sum1 = 0.f;
#pragma unroll
        for (int nt = 0; nt < 8; nt++) {
#pragma unroll
            for (int e = 0; e < 4; e++) {
                float s = sacc[nt][e];
                float p = (s == -CUDART_INF_F) ? 0.f
                         : __expf(s - ((e < 2) ? mm0 : mm1));
                sacc[nt][e] = p;
                if (e < 2) sum0 += p; else sum1 += p;
            }
        }
        sum0 += __shfl_xor_sync(0xffffffffu, sum0, 1);
        sum0 += __shfl_xor_sync(0xffffffffu, sum0, 2);
        sum1 += __shfl_xor_sync(0xffffffffu, sum1, 1);
        sum1 += __shfl_xor_sync(0xffffffffu, sum1, 2);

        l0s = l0s * c0 + sum0;  m0 = mn0;
        l1s = l1s * c1 + sum1;  m1 = mn1;

#pragma unroll
        for (int nt = 0; nt < 16; nt++) {
            oacc[nt][0] *= c0; oacc[nt][1] *= c0;
            oacc[nt][2] *= c1; oacc[nt][3] *= c1;
        }

#pragma unroll
        for (int kt = 0; kt < 4; kt++) {
            uint32_t aph[4], apl[4];
            split2_pack(sacc[2 * kt][0],     sacc[2 * kt][1],     aph[0], apl[0]);
            split2_pack(sacc[2 * kt][2],     sacc[2 * kt][3],     aph[1], apl[1]);
            split2_pack(sacc[2 * kt + 1][0], sacc[2 * kt + 1][1], aph[2], apl[2]);
            split2_pack(sacc[2 * kt + 1][2], sacc[2 * kt + 1][3], aph[3], apl[3]);
            const int kc = kt * 16;
#pragma unroll
            for (int p = 0; p < 8; p++) {
                uint32_t voff = ((kc + vKey) * QST + p * 16 + vDim) * 2;
                uint32_t vh4[4], vl4[4];
                ldsm_x4_trans(vh4, uVh_ + voff);
                ldsm_x4_trans(vl4, uVl_ + voff);
                uint32_t bh0[2] = {vh4[0], vh4[1]}, bh1[2] = {vh4[2], vh4[3]};
                uint32_t bl0[2] = {vl4[0], vl4[1]}, bl1[2] = {vl4[2], vl4[3]};
                mma_bf16(oacc[2 * p],     apl, bh0);
                mma_bf16(oacc[2 * p],     aph, bl0);
                mma_bf16(oacc[2 * p],     aph, bh0);
                mma_bf16(oacc[2 * p + 1], apl, bh1);
                mma_bf16(oacc[2 * p + 1], aph, bl1);
                mma_bf16(oacc[2 * p + 1], aph, bh1);
            }
        }
        __syncthreads();
        cur ^= 1;
    }

    float inv0 = __fdiv_rn(1.f, l0s);
    float inv1 = __fdiv_rn(1.f, l1s);
    const int row0 = t0 + r0 + g;
#pragma unroll
    for (int nt = 0; nt < 16; nt++) {
        int c = h * 128 + nt * 8 + tig * 2;
        uint32_t hi, lo;
        split2_pack(oacc[nt][0] * inv0, oacc[nt][1] * inv0, hi, lo);
        *(uint32_t*)(Yh + (size_t)row0 * 2048 + c) = hi;
        *(uint32_t*)(Yl + (size_t)row0 * 2048 + c) = lo;
        split2_pack(oacc[nt][2] * inv1, oacc[nt][3] * inv1, hi, lo);
        *(uint32_t*)(Yh + (size_t)(row0 + 8) * 2048 + c) = hi;
        *(uint32_t*)(Yl + (size_t)(row0 + 8) * 2048 + c) = lo;
    }
}

// ---------------------------------------------------------------------------
// Launch — multi-stream fork/join (graph-capture compatible via events).
// ---------------------------------------------------------------------------
extern "C" void kernel_launch(void* const* d_in, const int* in_sizes, int n_in,
                              void* d_out, int out_size)
{
    const float* x     = (const float*)d_in[0];
    const float* cosb  = (const float*)d_in[1];
    const float* sinb  = (const float*)d_in[2];
    const float* Wq    = (const float*)d_in[3];
    const float* Wk    = (const float*)d_in[4];
    const float* Wv    = (const float*)d_in[5];
    const float* Wproj = (const float*)d_in[6];
    float* out = (float*)d_out;

    const int T = in_sizes[0] / C_DIM;

    float *pq, *pk, *pv;
    __nv_bfloat16 *pxh, *pxl, *pyh, *pyl, *pwqh, *pwql, *pwph, *pwpl;
    __nv_bfloat16 *pQh, *pQl, *pKh, *pKl, *pVh, *pVl;
    cudaGetSymbolAddress((void**)&pq, g_q);
    cudaGetSymbolAddress((void**)&pk, g_k);
    cudaGetSymbolAddress((void**)&pv, g_v);
    cudaGetSymbolAddress((void**)&pxh, g_xh);
    cudaGetSymbolAddress((void**)&pxl, g_xl);
    cudaGetSymbolAddress((void**)&pyh, g_yh);
    cudaGetSymbolAddress((void**)&pyl, g_yl);
    cudaGetSymbolAddress((void**)&pwqh, g_wqh);
    cudaGetSymbolAddress((void**)&pwql, g_wql);
    cudaGetSymbolAddress((void**)&pwph, g_wph);
    cudaGetSymbolAddress((void**)&pwpl, g_wpl);
    cudaGetSymbolAddress((void**)&pQh, g_Qph);
    cudaGetSymbolAddress((void**)&pQl, g_Qpl);
    cudaGetSymbolAddress((void**)&pKh, g_Kph);
    cudaGetSymbolAddress((void**)&pKl, g_Kpl);
    cudaGetSymbolAddress((void**)&pVh, g_Vph);
    cudaGetSymbolAddress((void**)&pVl, g_Vpl);

    cudaFuncSetAttribute(attn_tc_kernel, cudaFuncAttributeMaxDynamicSharedMemorySize,
                         ATT_SMEM);
    cudaFuncSetAttribute(gemm_bf16x3_kernel,
                         cudaFuncAttributeMaxDynamicSharedMemorySize, GEMM_SMEM);

    dim3 blk(256);
    const int nx4 = T * 2048 / 4;

    // --- fork: 3 worker streams + origin (default) ---
    cudaStream_t s0 = 0, sA, sB, sC;
    cudaStreamCreateWithFlags(&sA, cudaStreamNonBlocking);
    cudaStreamCreateWithFlags(&sB, cudaStreamNonBlocking);
    cudaStreamCreateWithFlags(&sC, cudaStreamNonBlocking);
    cudaEvent_t evRoot, evA, evB, evC;
    cudaEventCreateWithFlags(&evRoot, cudaEventDisableTiming);
    cudaEventCreateWithFlags(&evA, cudaEventDisableTiming);
    cudaEventCreateWithFlags(&evB, cudaEventDisableTiming);
    cudaEventCreateWithFlags(&evC, cudaEventDisableTiming);

    cudaEventRecord(evRoot, s0);
    cudaStreamWaitEvent(sA, evRoot, 0);
    cudaStreamWaitEvent(sB, evRoot, 0);
    cudaStreamWaitEvent(sC, evRoot, 0);

    // --- stream A: Q-projection chain (tensor pipe) ---
    split_bf16_kernel<<<(nx4 + 255) / 256, blk, 0, sA>>>(x, pxh, pxl, nx4);
    transpose_split_kernel<<<dim3(2048 / 32, 2048 / 32), blk, 0, sA>>>(
        Wq, pwqh, pwql, 2048, 2048);
    gemm_bf16x3_kernel<<<dim3(2048 / 128, T / 128), blk, GEMM_SMEM, sA>>>(
        pxh, pxl, pwqh, pwql, pq, T, 2048, 2048);
    rope_rms_q_kernel<<<dim3(T, N_HEAD), 64, 0, sA>>>(pq, cosb, sinb, pQh, pQl, T);
    cudaEventRecord(evA, sA);

    // --- stream B: K chain (FMA pipe, frozen) ---
    sgemm_kv_kernel<<<dim3(512 / 32, T / 32), blk, 0, sB>>>(x, Wk, pk, T, 512, 2048);
    rope_rms_quant_k_kernel<<<dim3(T, N_KVH), 64, 0, sB>>>(pk, cosb, sinb, pKh, pKl, T);
    cudaEventRecord(evB, sB);

    // --- stream C: V chain (FMA pipe, frozen) + Wproj transpose ---
    sgemm_kv_kernel<<<dim3(512 / 32, T / 32), blk, 0, sC>>>(x, Wv, pv, T, 512, 2048);
    quant_v_kernel<<<dim3(T, N_KVH), 64, 0, sC>>>(pv, pVh, pVl, T);
    transpose_split_kernel<<<dim3(2048 / 32, 2048 / 32), blk, 0, sC>>>(
        Wproj, pwph, pwpl, 2048, 2048);
    cudaEventRecord(evC, sC);

    // --- join on origin, then attention + output projection ---
    cudaStreamWaitEvent(s0, evA, 0);
    cudaStreamWaitEvent(s0, evB, 0);
    cudaStreamWaitEvent(s0, evC, 0);

    attn_tc_kernel<<<dim3(T / 128, N_HEAD), blk, ATT_SMEM, s0>>>(
        pQh, pQl, pKh, pKl, pVh, pVl, pyh, pyl, T);

    gemm_bf16x3_kernel<<<dim3(2048 / 128, T / 128), blk, GEMM_SMEM, s0>>>(
        pyh, pyl, pwph, pwpl, out, T, 2048, 2048);

    cudaEventDestroy(evRoot);
    cudaEventDestroy(evA);
    cudaEventDestroy(evB);
    cudaEventDestroy(evC);
    cudaStreamDestroy(sA);
    cudaStreamDestroy(sB);
    cudaStreamDestroy(sC);
}

// round 16
// speedup vs baseline: 1.0967x; 1.0967x over previous
#include <cuda_runtime.h>
#include <cuda_bf16.h>
#include <math_constants.h>
#include <cstdint>

// ---------------------------------------------------------------------------
// Problem constants
// ---------------------------------------------------------------------------
#define T_MAX   8192
#define C_DIM   2048
#define N_HEAD  16
#define N_KVH   4
#define HDIM    128
#define WIN     1024
#define RMS_EPS 1.1920929e-07f

// ---------------------------------------------------------------------------
// Scratch (device globals; no runtime allocation allowed)
// ---------------------------------------------------------------------------
__device__ float g_q[(size_t)T_MAX * 2048];            // x @ Wq (fp32)
__device__ float g_k[(size_t)T_MAX * 512];
__device__ float g_v[(size_t)T_MAX * 512];
// bf16 hi/lo planes
__device__ __nv_bfloat16 g_xh[(size_t)T_MAX * 2048];
__device__ __nv_bfloat16 g_xl[(size_t)T_MAX * 2048];
__device__ __nv_bfloat16 g_yh[(size_t)T_MAX * 2048];
__device__ __nv_bfloat16 g_yl[(size_t)T_MAX * 2048];
__device__ __nv_bfloat16 g_wqh[(size_t)2048 * 2048];
__device__ __nv_bfloat16 g_wql[(size_t)2048 * 2048];
__device__ __nv_bfloat16 g_wph[(size_t)2048 * 2048];
__device__ __nv_bfloat16 g_wpl[(size_t)2048 * 2048];
__device__ __nv_bfloat16 g_Qph[(size_t)N_HEAD * T_MAX * HDIM];
__device__ __nv_bfloat16 g_Qpl[(size_t)N_HEAD * T_MAX * HDIM];
__device__ __nv_bfloat16 g_Kph[(size_t)N_KVH * T_MAX * HDIM];
__device__ __nv_bfloat16 g_Kpl[(size_t)N_KVH * T_MAX * HDIM];
__device__ __nv_bfloat16 g_Vph[(size_t)N_KVH * T_MAX * HDIM];
__device__ __nv_bfloat16 g_Vpl[(size_t)N_KVH * T_MAX * HDIM];

// ---------------------------------------------------------------------------
// PTX helpers
// ---------------------------------------------------------------------------
__device__ __forceinline__ void mma_bf16(float* d,
                                         const uint32_t* a, const uint32_t* b) {
    asm volatile(
        "mma.sync.aligned.m16n8k16.row.col.f32.bf16.bf16.f32 "
        "{%0,%1,%2,%3}, {%4,%5,%6,%7}, {%8,%9}, {%0,%1,%2,%3};"
        : "+f"(d[0]), "+f"(d[1]), "+f"(d[2]), "+f"(d[3])
        : "r"(a[0]), "r"(a[1]), "r"(a[2]), "r"(a[3]),
          "r"(b[0]), "r"(b[1]));
}
__device__ __forceinline__ void ldsm_x4(uint32_t* r, uint32_t saddr) {
    asm volatile(
        "ldmatrix.sync.aligned.m8n8.x4.shared.b16 {%0,%1,%2,%3}, [%4];"
        : "=r"(r[0]), "=r"(r[1]), "=r"(r[2]), "=r"(r[3]) : "r"(saddr));
}
__device__ __forceinline__ void ldsm_x4_trans(uint32_t* r, uint32_t saddr) {
    asm volatile(
        "ldmatrix.sync.aligned.m8n8.x4.trans.shared.b16 {%0,%1,%2,%3}, [%4];"
        : "=r"(r[0]), "=r"(r[1]), "=r"(r[2]), "=r"(r[3]) : "r"(saddr));
}
__device__ __forceinline__ void cp_async16(uint32_t s, const void* g) {
    asm volatile("cp.async.cg.shared.global [%0], [%1], 16;" :: "r"(s), "l"(g));
}
#define CP_COMMIT() asm volatile("cp.async.commit_group;" ::: "memory")
#define CP_WAIT0()  asm volatile("cp.async.wait_group 0;" ::: "memory")
#define CP_WAIT1()  asm volatile("cp.async.wait_group 1;" ::: "memory")

__device__ __forceinline__ uint32_t smem_to_u32(const void* p) {
    uint32_t a;
    asm("{ .reg .u64 t; cvta.to.shared.u64 t, %1; cvt.u32.u64 %0, t; }"
        : "=r"(a) : "l"(p));
    return a;
}
__device__ __forceinline__ uint32_t pack_bf16(__nv_bfloat16 a, __nv_bfloat16 b) {
    return (uint32_t)__bfloat16_as_ushort(a) |
           ((uint32_t)__bfloat16_as_ushort(b) << 16);
}
__device__ __forceinline__ void split2_pack(float x, float y,
                                            uint32_t& hi, uint32_t& lo) {
    __nv_bfloat16 hx = __float2bfloat16(x);
    __nv_bfloat16 hy = __float2bfloat16(y);
    __nv_bfloat16 lx = __float2bfloat16(__fsub_rn(x, __bfloat162float(hx)));
    __nv_bfloat16 ly = __float2bfloat16(__fsub_rn(y, __bfloat162float(hy)));
    hi = pack_bf16(hx, hy);
    lo = pack_bf16(lx, ly);
}
__device__ __forceinline__ void split1(float x, __nv_bfloat16& h, __nv_bfloat16& l) {
    h = __float2bfloat16(x);
    l = __float2bfloat16(__fsub_rn(x, __bfloat162float(h)));
}

// ---------------------------------------------------------------------------
// fp32 -> (hi, lo) bf16 split, elementwise. n4 = n/4.
// ---------------------------------------------------------------------------
__global__ void split_bf16_kernel(const float* __restrict__ X,
                                  __nv_bfloat16* __restrict__ H,
                                  __nv_bfloat16* __restrict__ L, int n4)
{
    int i = blockIdx.x * blockDim.x + threadIdx.x;
    if (i >= n4) return;
    float4 v = ((const float4*)X)[i];
    float xs[4] = {v.x, v.y, v.z, v.w};
    union { __nv_bfloat16 b[4]; uint2 u; } ph, pl;
#pragma unroll
    for (int j = 0; j < 4; j++) split1(xs[j], ph.b[j], pl.b[j]);
    *(uint2*)(H + (size_t)i * 4) = ph.u;
    *(uint2*)(L + (size_t)i * 4) = pl.u;
}

// ---------------------------------------------------------------------------
// W [K, N] fp32 -> Wt hi/lo bf16 [N, K] (transpose + split). 32x32 tiles.
// ---------------------------------------------------------------------------
__global__ void transpose_split_kernel(const float* __restrict__ W,
                                       __nv_bfloat16* __restrict__ Th,
                                       __nv_bfloat16* __restrict__ Tl,
                                       int K, int N)
{
    __shared__ float tile[32][33];
    int k0 = blockIdx.y * 32, n0 = blockIdx.x * 32;
    int tx = threadIdx.x & 31, ty = threadIdx.x >> 5;
#pragma unroll
    for (int r = ty; r < 32; r += 8)
        tile[r][tx] = W[(size_t)(k0 + r) * N + n0 + tx];
    __syncthreads();
#pragma unroll
    for (int r = ty; r < 32; r += 8) {
        __nv_bfloat16 h, l;
        split1(tile[tx][r], h, l);
        Th[(size_t)(n0 + r) * K + k0 + tx] = h;
        Tl[(size_t)(n0 + r) * K + k0 + tx] = l;
    }
}

// ---------------------------------------------------------------------------
// bf16x3 tensor-core GEMM (unchanged from Round 12/13/14).
// ---------------------------------------------------------------------------
#define GST 40
#define GPL (128 * GST * 2)
#define GSTG (4 * GPL)
#define GEMM_SMEM (2 * GSTG)

__global__ __launch_bounds__(256, 2) void gemm_bf16x3_kernel(
    const __nv_bfloat16* __restrict__ Ah, const __nv_bfloat16* __restrict__ Al,
    const __nv_bfloat16* __restrict__ Bh, const __nv_bfloat16* __restrict__ Bl,
    float* __restrict__ C, int M, int N, int K)
{
    extern __shared__ __nv_bfloat16 gsm[];
    const uint32_t sbu = smem_to_u32(gsm);

    const int tid  = threadIdx.x;
    const int lane = tid & 31;
    const int wid  = tid >> 5;
    const int wm   = wid & 1;
    const int wn   = wid >> 1;

    const __nv_bfloat16* gAh = Ah + (size_t)blockIdx.y * 128 * K;
    const __nv_bfloat16* gAl = Al + (size_t)blockIdx.y * 128 * K;
    const __nv_bfloat16* gBh = Bh + (size_t)blockIdx.x * 128 * K;
    const __nv_bfloat16* gBl = Bl + (size_t)blockIdx.x * 128 * K;

    const int srow0 = tid >> 2, sc0 = (tid & 3) * 8;
    const int srow1 = (tid + 256) >> 2, sc1 = ((tid + 256) & 3) * 8;

    float acc[4][4][4];
#pragma unroll
    for (int mt = 0; mt < 4; mt++)
#pragma unroll
        for (int nt = 0; nt < 4; nt++)
#pragma unroll
            for (int e = 0; e < 4; e++) acc[mt][nt][e] = 0.f;

    const uint32_t aRow = (lane & 15);
    const uint32_t aCol = (lane & 16) ? 8 : 0;
    const uint32_t bRow = (lane & 7) + ((lane & 16) >> 1);
    const uint32_t bCol = (lane & 8);

    const int nIter = K / 32;

    {
        uint32_t base = sbu;
        size_t go0 = (size_t)srow0 * K + sc0;
        size_t go1 = (size_t)srow1 * K + sc1;
        uint32_t so0 = base + (srow0 * GST + sc0) * 2;
        uint32_t so1 = base + (srow1 * GST + sc1) * 2;
        cp_async16(so0,           gAh + go0);
        cp_async16(so0 + GPL,     gAl + go0);
        cp_async16(so0 + 2 * GPL, gBh + go0);
        cp_async16(so0 + 3 * GPL, gBl + go0);
        cp_async16(so1,           gAh + go1);
        cp_async16(so1 + GPL,     gAl + go1);
        cp_async16(so1 + 2 * GPL, gBh + go1);
        cp_async16(so1 + 3 * GPL, gBl + go1);
        CP_COMMIT();
    }

    int cur = 0;
    for (int it = 0; it < nIter; it++) {
        CP_WAIT0();
        __syncthreads();

        if (it + 1 < nIter) {
            int k0n = (it + 1) * 32;
            uint32_t base = sbu + (cur ^ 1) * GSTG;
            size_t go0 = (size_t)srow0 * K + k0n + sc0;
            size_t go1 = (size_t)srow1 * K + k0n + sc1;
            uint32_t so0 = base + (srow0 * GST + sc0) * 2;
            uint32_t so1 = base + (srow1 * GST + sc1) * 2;
            cp_async16(so0,           gAh + go0);
            cp_async16(so0 + GPL,     gAl + go0);
            cp_async16(so0 + 2 * GPL, gBh + go0);
            cp_async16(so0 + 3 * GPL, gBl + go0);
            cp_async16(so1,           gAh + go1);
            cp_async16(so1 + GPL,     gAl + go1);
            cp_async16(so1 + 2 * GPL, gBh + go1);
            cp_async16(so1 + 3 * GPL, gBl + go1);
            CP_COMMIT();
        }

        const uint32_t bA = sbu + cur * GSTG;
        const uint32_t bAl_ = bA + GPL;
        const uint32_t bB = bA + 2 * GPL;
        const uint32_t bBl_ = bA + 3 * GPL;

#pragma unroll
        for (int ks = 0; ks < 2; ks++) {
            const int ko = ks * 16;
            uint32_t bh[4][2], bl[4][2];
#pragma unroll
            for (int p = 0; p < 2; p++) {
                uint32_t roff = ((wn * 32 + p * 16 + bRow) * GST + ko + bCol) * 2;
                uint32_t t4[4];
                ldsm_x4(t4, bB + roff);
                bh[2 * p][0] = t4[0]; bh[2 * p][1] = t4[1];
                bh[2 * p + 1][0] = t4[2]; bh[2 * p + 1][1] = t4[3];
                ldsm_x4(t4, bBl_ + roff);
                bl[2 * p][0] = t4[0]; bl[2 * p][1] = t4[1];
                bl[2 * p + 1][0] = t4[2]; bl[2 * p + 1][1] = t4[3];
            }
#pragma unroll
            for (int mt = 0; mt < 4; mt++) {
                uint32_t aoff = ((wm * 64 + mt * 16 + aRow) * GST + ko + aCol) * 2;
                uint32_t ah[4], al[4];
                ldsm_x4(ah, bA + aoff);
                ldsm_x4(al, bAl_ + aoff);
#pragma unroll
                for (int nt = 0; nt < 4; nt++) {
                    mma_bf16(acc[mt][nt], al, bh[nt]);
                    mma_bf16(acc[mt][nt], ah, bl[nt]);
                    mma_bf16(acc[mt][nt], ah, bh[nt]);
                }
            }
        }
        cur ^= 1;
    }

    const int g2 = lane >> 2, tig2 = lane & 3;
#pragma unroll
    for (int mt = 0; mt < 4; mt++) {
#pragma unroll
        for (int nt = 0; nt < 4; nt++) {
            int r = blockIdx.y * 128 + wm * 64 + mt * 16 + g2;
            int c = blockIdx.x * 128 + wn * 32 + nt * 8 + tig2 * 2;
            *(float2*)(C + (size_t)r * N + c) =
                make_float2(acc[mt][nt][0], acc[mt][nt][1]);
            *(float2*)(C + (size_t)(r + 8) * N + c) =
                make_float2(acc[mt][nt][2], acc[mt][nt][3]);
        }
    }
}

// ---------------------------------------------------------------------------
// K/V projection SGEMM — *** ARITHMETIC FROZEN *** (LLVM-interleaved-16).
// Round 14 WIN version (f32x2 experiment reverted).
// ---------------------------------------------------------------------------
#define KVST 36

__global__ __launch_bounds__(256) void sgemm_kv_kernel(
    const float* __restrict__ A, const float* __restrict__ B,
    float* __restrict__ C, int M, int N, int K)
{
    __shared__ float As[2][32][KVST];   // [buf][k][m]
    __shared__ float Bs[2][32][KVST];   // [buf][k][n]

    const int tid = threadIdx.x;
    const int tx  = tid & 31;
    const int ty  = tid >> 5;
    const int bx  = blockIdx.x;
    const int by  = blockIdx.y;

    const float* Ab = A + (size_t)(by * 32) * K;
    const float* Bb = B + (size_t)(bx * 32);

    const int am = tid >> 3;
    const int ak = (tid & 7) << 2;
    const int bk = tid >> 3;
    const int bn = (tid & 7) << 2;

    float part[4][16];
#pragma unroll
    for (int r = 0; r < 4; r++)
#pragma unroll
        for (int j = 0; j < 16; j++) part[r][j] = 0.f;

    const int nIter = K / 32;
    float4 a_reg = *(const float4*)(Ab + (size_t)am * K + ak);
    float4 b_reg = *(const float4*)(Bb + (size_t)bk * N + bn);

    int buf = 0;
    for (int it = 0; it < nIter; it++) {
        As[buf][ak + 0][am] = a_reg.x;
        As[buf][ak + 1][am] = a_reg.y;
        As[buf][ak + 2][am] = a_reg.z;
        As[buf][ak + 3][am] = a_reg.w;
        *(float4*)&Bs[buf][bk][bn] = b_reg;
        __syncthreads();

        if (it + 1 < nIter) {
            int k0n = (it + 1) * 32;
            a_reg = *(const float4*)(Ab + (size_t)am * K + k0n + ak);
            b_reg = *(const float4*)(Bb + (size_t)(k0n + bk) * N + bn);
        }

#pragma unroll
        for (int j = 0; j < 16; j++) {
            float4 a0 = *(const float4*)&As[buf][j][ty * 4];
            float  b0 = Bs[buf][j][tx];
            part[0][j] = __fmaf_rn(a0.x, b0, part[0][j]);
            part[1][j] = __fmaf_rn(a0.y, b0, part[1][j]);
            part[2][j] = __fmaf_rn(a0.z, b0, part[2][j]);
            part[3][j] = __fmaf_rn(a0.w, b0, part[3][j]);
            float4 a1 = *(const float4*)&As[buf][j + 16][ty * 4];
            float  b1 = Bs[buf][j + 16][tx];
            part[0][j] = __fmaf_rn(a1.x, b1, part[0][j]);
            part[1][j] = __fmaf_rn(a1.y, b1, part[1][j]);
            part[2][j] = __fmaf_rn(a1.z, b1, part[2][j]);
            part[3][j] = __fmaf_rn(a1.w, b1, part[3][j]);
        }
        buf ^= 1;
    }

#pragma unroll
    for (int r = 0; r < 4; r++) {
        float w[4];
#pragma unroll
        for (int l = 0; l < 4; l++)
            w[l] = __fadd_rn(__fadd_rn(part[r][l],     part[r][4 + l]),
                             __fadd_rn(part[r][8 + l], part[r][12 + l]));
        float res = __fadd_rn(__fadd_rn(w[0], w[1]), __fadd_rn(w[2], w[3]));
        C[(size_t)(by * 32 + ty * 4 + r) * N + bx * 32 + tx] = res;
    }
}

__device__ __forceinline__ float rsqrt_rn(float x) {
    return __fdiv_rn(1.0f, __fsqrt_rn(x));
}

// ---------------------------------------------------------------------------
// RoPE + RMS for Q -> bf16 hi/lo planes.
// ---------------------------------------------------------------------------
__global__ void rope_rms_q_kernel(
    const float* __restrict__ X, const float* __restrict__ cosb,
    const float* __restrict__ sinb,
    __nv_bfloat16* __restrict__ Qh, __nv_bfloat16* __restrict__ Ql, int T)
{
    const int t = blockIdx.x, h = blockIdx.y, d = threadIdx.x;
    const float* row = X + (size_t)t * 2048 + h * 128;
    float x1 = row[d], x2 = row[d + 64];
    float c = cosb[t * 64 + d], s = sinb[t * 64 + d];
    float o1 = __fadd_rn(__fmul_rn(x1, c), __fmul_rn(x2, s));
    float o2 = __fsub_rn(__fmul_rn(x2, c), __fmul_rn(x1, s));

    float ss = __fadd_rn(__fmul_rn(o1, o1), __fmul_rn(o2, o2));
#pragma unroll
    for (int o = 16; o > 0; o >>= 1) ss += __shfl_down_sync(0xffffffffu, ss, o);
    __shared__ float sh[2];
    if ((d & 31) == 0) sh[d >> 5] = ss;
    __syncthreads();
    float ms = __fmul_rn(__fadd_rn(sh[0], sh[1]), 0.0078125f);
    float r = rsqrt_rn(__fadd_rn(ms, RMS_EPS));

    size_t base = ((size_t)h * T + t) * 128;
    __nv_bfloat16 hh, ll;
    split1(__fmul_rn(o1, r), hh, ll);
    Qh[base + d] = hh;  Ql[base + d] = ll;
    split1(__fmul_rn(o2, r), hh, ll);
    Qh[base + d + 64] = hh;  Ql[base + d + 64] = ll;
}

// ---------------------------------------------------------------------------
// RoPE + RMS + quant for K — frozen fp32 chain, then split to planes.
// ---------------------------------------------------------------------------
__global__ void rope_rms_quant_k_kernel(
    const float* __restrict__ X, const float* __restrict__ cosb,
    const float* __restrict__ sinb,
    __nv_bfloat16* __restrict__ Kh, __nv_bfloat16* __restrict__ Kl, int T)
{
    const int t = blockIdx.x, h = blockIdx.y, d = threadIdx.x;
    const float* row = X + (size_t)t * 512 + h * 128;
    float x1 = row[d], x2 = row[d + 64];
    float c = cosb[t * 64 + d], s = sinb[t * 64 + d];
    float o1 = __fadd_rn(__fmul_rn(x1, c), __fmul_rn(x2, s));
    float o2 = __fsub_rn(__fmul_rn(x2, c), __fmul_rn(x1, s));

    __shared__ float sh[4];
    float ss = __fadd_rn(__fmul_rn(o1, o1), __fmul_rn(o2, o2));
#pragma unroll
    for (int o = 16; o > 0; o >>= 1) ss += __shfl_down_sync(0xffffffffu, ss, o);
    if ((d & 31) == 0) sh[d >> 5] = ss;
    __syncthreads();
    float ms = __fmul_rn(__fadd_rn(sh[0], sh[1]), 0.0078125f);
    float r = rsqrt_rn(__fadd_rn(ms, RMS_EPS));
    float k1 = __fmul_rn(o1, r), k2 = __fmul_rn(o2, r);

    float m = fmaxf(fabsf(k1), fabsf(k2));
#pragma unroll
    for (int o = 16; o > 0; o >>= 1) m = fmaxf(m, __shfl_down_sync(0xffffffffu, m, o));
    if ((d & 31) == 0) sh[2 + (d >> 5)] = m;
    __syncthreads();
    float sq = fmaxf(__fdiv_rn(fmaxf(sh[2], sh[3]), 3.0f), 1e-8f);
    float q1 = __fmul_rn(fminf(fmaxf(rintf(__fdiv_rn(k1, sq)), -3.f), 3.f), sq);
    float q2 = __fmul_rn(fminf(fmaxf(rintf(__fdiv_rn(k2, sq)), -3.f), 3.f), sq);

    size_t base = ((size_t)h * T + t) * 128;
    __nv_bfloat16 hh, ll;
    split1(q1, hh, ll);
    Kh[base + d] = hh;  Kl[base + d] = ll;
    split1(q2, hh, ll);
    Kh[base + d + 64] = hh;  Kl[base + d + 64] = ll;
}

// ---------------------------------------------------------------------------
// Quant V — frozen fp32 chain, then split to planes.
// ---------------------------------------------------------------------------
__global__ void quant_v_kernel(
    const float* __restrict__ X,
    __nv_bfloat16* __restrict__ Vh, __nv_bfloat16* __restrict__ Vl, int T)
{
    const int t = blockIdx.x, h = blockIdx.y, d = threadIdx.x;
    const float* row = X + (size_t)t * 512 + h * 128;
    float v1 = row[d], v2 = row[d + 64];

    __shared__ float sh[2];
    float m = fmaxf(fabsf(v1), fabsf(v2));
#pragma unroll
    for (int o = 16; o > 0; o >>= 1) m = fmaxf(m, __shfl_down_sync(0xffffffffu, m, o));
    if ((d & 31) == 0) sh[d >> 5] = m;
    __syncthreads();
    float sq = fmaxf(__fdiv_rn(fmaxf(sh[0], sh[1]), 3.0f), 1e-8f);
    float q1 = __fmul_rn(fminf(fmaxf(rintf(__fdiv_rn(v1, sq)), -3.f), 3.f), sq);
    float q2 = __fmul_rn(fminf(fmaxf(rintf(__fdiv_rn(v2, sq)), -3.f), 3.f), sq);

    size_t base = ((size_t)h * T + t) * 128;
    __nv_bfloat16 hh, ll;
    split1(q1, hh, ll);
    Vh[base + d] = hh;  Vl[base + d] = ll;
    split1(q2, hh, ll);
    Vh[base + d + 64] = hh;  Vl[base + d + 64] = ll;
}

// ---------------------------------------------------------------------------
// Tensor-core flash attention v4: 64 queries / 4 warps / single KV buffer ->
// smem 104448 B -> 2 CTAs/SM (cross-CTA hiding of softmax + load bubbles).
// Per-row arithmetic, mma order, masking: identical to v3 (bit-exact output).
// ---------------------------------------------------------------------------
#define QST 136
#define QPL2 (64 * QST * 2)              // Q plane bytes = 17408
#define KPL  (64 * QST * 2)              // K/V plane bytes = 17408
#define ATT_SMEM (2 * QPL2 + 4 * KPL)    // 104448

__global__ __launch_bounds__(128) void attn_tc_kernel(
    const __nv_bfloat16* __restrict__ Qh, const __nv_bfloat16* __restrict__ Ql,
    const __nv_bfloat16* __restrict__ Kh, const __nv_bfloat16* __restrict__ Kl,
    const __nv_bfloat16* __restrict__ Vh, const __nv_bfloat16* __restrict__ Vl,
    __nv_bfloat16* __restrict__ Yh, __nv_bfloat16* __restrict__ Yl, int T)
{
    extern __shared__ __nv_bfloat16 sm[];
    const uint32_t uQ  = smem_to_u32(sm);
    const uint32_t uQl = uQ + QPL2;
    const uint32_t uKV = uQ + 2 * QPL2;
    const uint32_t uKh_ = uKV;
    const uint32_t uKl_ = uKV + KPL;
    const uint32_t uVh_ = uKV + 2 * KPL;
    const uint32_t uVl_ = uKV + 3 * KPL;

    const int tid  = threadIdx.x;
    const int lane = tid & 31;
    const int wr   = tid >> 5;          // 0..3, warp rows wr*16..+15
    const int g    = lane >> 2;
    const int tig  = lane & 3;
    const int h    = blockIdx.y;
    const int t0   = blockIdx.x << 6;   // 64 queries
    const int hk   = h >> 2;
    const int r0   = wr * 16;

    const uint32_t aRow = (lane & 15);
    const uint32_t aCol = (lane & 16) ? 8 : 0;
    const uint32_t bRow = (lane & 7) + ((lane & 16) >> 1);
    const uint32_t bCol = (lane & 8);
    const uint32_t vKey = (lane & 7) + ((lane >> 3) & 1) * 8;
    const uint32_t vDim = (lane >> 4) * 8;

    const __nv_bfloat16* gQh = Qh + ((size_t)h * T + t0) * 128;
    const __nv_bfloat16* gQl = Ql + ((size_t)h * T + t0) * 128;
    const __nv_bfloat16* gKh = Kh + (size_t)hk * T * 128;
    const __nv_bfloat16* gKl = Kl + (size_t)hk * T * 128;
    const __nv_bfloat16* gVh = Vh + (size_t)hk * T * 128;
    const __nv_bfloat16* gVl = Vl + (size_t)hk * T * 128;
    const float scale = 0.08838834764831845f;

    int kb0 = t0 - WIN; if (kb0 < 0) kb0 = 0;
    const int kbend = t0;               // last block covering rows t0..t0+63

    // ---- prologue: stage Q (2 planes x 1024 chunks) + first KV block ----
#pragma unroll
    for (int i = 0; i < 16; i++) {
        int cidx = tid + 128 * i;               // 0..2047
        int plane = cidx >> 10, rem = cidx & 1023;
        int row = rem >> 4, ch = rem & 15;
        const __nv_bfloat16* src = (plane ? gQl : gQh) + (size_t)row * 128 + ch * 8;
        cp_async16(uQ + plane * QPL2 + (row * QST + ch * 8) * 2, src);
    }
    {
        const __nv_bfloat16* srcs[4] = {gKh, gKl, gVh, gVl};
#pragma unroll
        for (int i = 0; i < 32; i++) {
            int cidx = tid + 128 * i;           // 0..4095
            int plane = cidx >> 10, rem = cidx & 1023;
            int row = rem >> 4, ch = rem & 15;
            cp_async16(uKV + plane * KPL + (row * QST + ch * 8) * 2,
                       srcs[plane] + (size_t)(kb0 + row) * 128 + ch * 8);
        }
    }
    CP_COMMIT();

    float m0 = -CUDART_INF_F, m1 = -CUDART_INF_F, l0s = 0.f, l1s = 0.f;
    float oacc[16][4];
#pragma unroll
    for (int nt = 0; nt < 16; nt++)
#pragma unroll
        for (int e = 0; e < 4; e++) oacc[nt][e] = 0.f;

    for (int kb = kb0; kb <= kbend; kb += 64) {
        CP_WAIT0();
        __syncthreads();

        // ---- S = Q @ K^T (bf16x3) ----
        float sacc[8][4];
#pragma unroll
        for (int nt = 0; nt < 8; nt++)
#pragma unroll
            for (int e = 0; e < 4; e++) sacc[nt][e] = 0.f;

#pragma unroll
        for (int kt = 0; kt < 8; kt++) {
            const int kc = kt * 16;
            uint32_t qoff = ((r0 + aRow) * QST + kc + aCol) * 2;
            uint32_t ah[4], al[4];
            ldsm_x4(ah, uQ + qoff);
            ldsm_x4(al, uQl + qoff);

            uint32_t kfh[8][2], kfl[8][2];
#pragma unroll
            for (int p = 0; p < 4; p++) {
                uint32_t koff = ((p * 16 + bRow) * QST + kc + bCol) * 2;
                uint32_t t4[4];
                ldsm_x4(t4, uKh_ + koff);
                kfh[2 * p][0] = t4[0]; kfh[2 * p][1] = t4[1];
                kfh[2 * p + 1][0] = t4[2]; kfh[2 * p + 1][1] = t4[3];
                ldsm_x4(t4, uKl_ + koff);
                kfl[2 * p][0] = t4[0]; kfl[2 * p][1] = t4[1];
                kfl[2 * p + 1][0] = t4[2]; kfl[2 * p + 1][1] = t4[3];
            }
#pragma unroll
            for (int nt = 0; nt < 8; nt++) {
                mma_bf16(sacc[nt], al, kfh[nt]);
                mma_bf16(sacc[nt], ah, kfl[nt]);
                mma_bf16(sacc[nt], ah, kfh[nt]);
            }
        }

        // ---- mask + scale, online softmax (identical arithmetic) ----
        const int row0 = t0 + r0 + g;
        const int row1 = row0 + 8;
        float rmax0 = -CUDART_INF_F, rmax1 = -CUDART_INF_F;
#pragma unroll
        for (int nt = 0; nt < 8; nt++) {
            int c0 = kb + nt * 8 + tig * 2;
#pragma unroll
            for (int e = 0; e < 4; e++) {
                int col = c0 + (e & 1);
                int row = (e < 2) ? row0 : row1;
                bool valid = (col <= row) && (col + WIN > row);
                float s = valid ? sacc[nt][e] * scale : -CUDART_INF_F;
                sacc[nt][e] = s;
                if (e < 2) rmax0 = fmaxf(rmax0, s);
                else       rmax1 = fmaxf(rmax1, s);
            }
        }
        rmax0 = fmaxf(rmax0, __shfl_xor_sync(0xffffffffu, rmax0, 1));
        rmax0 = fmaxf(rmax0, __shfl_xor_sync(0xffffffffu, rmax0, 2));
        rmax1 = fmaxf(rmax1, __shfl_xor_sync(0xffffffffu, rmax1, 1));
        rmax1 = fmaxf(rmax1, __shfl_xor_sync(0xffffffffu, rmax1, 2));

        float mn0 = fmaxf(m0, rmax0), mn1 = fmaxf(m1, rmax1);
        float mm0 = (mn0 == -CUDART_INF_F) ? 0.f : mn0;
        float mm1 = (mn1 == -CUDART_INF_F) ? 0.f : mn1;
        float c0 = __expf(m0 - mm0);
        float c1 = __expf(m1 - mm1);
        if (m0 == -CUDART_INF_F) c0 = (mn0 == -CUDART_INF_F) ? 1.f : 0.f;
        if (m1 == -CUDART_INF_F) c1 = (mn1 == -CUDART_INF_F) ? 1.f : 0.f;

        float sum0 = 0.f, sum1 = 0.f;
#pragma unroll
        for (int nt = 0; nt < 8; nt++) {
#pragma unroll
            for (int e = 0; e < 4; e++) {
                float s = sacc[nt][e];
                float p = (s == -CUDART_INF_F) ? 0.f
                         : __expf(s - ((e < 2) ? mm0 : mm1));
                sacc[nt][e] = p;
                if (e < 2) sum0 += p; else sum1 += p;
            }
        }
        sum0 += __shfl_xor_sync(0xffffffffu, sum0, 1);
        sum0 += __shfl_xor_sync(0xffffffffu, sum0, 2);
        sum1 += __shfl_xor_sync(0xffffffffu, sum1, 1);
        sum1 += __shfl_xor_sync(0xffffffffu, sum1, 2);

        l0s = l0s * c0 + sum0;  m0 = mn0;
        l1s = l1s * c1 + sum1;  m1 = mn1;

#pragma unroll
        for (int nt = 0; nt < 16; nt++) {
            oacc[nt][0] *= c0; oacc[nt][1] *= c0;
            oacc[nt][2] *= c1; oacc[nt][3] *= c1;
        }

        // ---- O += P @ V (bf16x3); V fragments via ldmatrix.trans ----
#pragma unroll
        for (int kt = 0; kt < 4; kt++) {
            uint32_t aph[4], apl[4];
            split2_pack(sacc[2 * kt][0],     sacc[2 * kt][1],     aph[0], apl[0]);
            split2_pack(sacc[2 * kt][2],     sacc[2 * kt][3],     aph[1], apl[1]);
            split2_pack(sacc[2 * kt + 1][0], sacc[2 * kt + 1][1], aph[2], apl[2]);
            split2_pack(sacc[2 * kt + 1][2], sacc[2 * kt + 1][3], aph[3], apl[3]);
            const int kc = kt * 16;
#pragma unroll
            for (int p = 0; p < 8; p++) {
                uint32_t voff = ((kc + vKey) * QST + p * 16 + vDim) * 2;
                uint32_t vh4[4], vl4[4];
                ldsm_x4_trans(vh4, uVh_ + voff);
                ldsm_x4_trans(vl4, uVl_ + voff);
                uint32_t bh0[2] = {vh4[0], vh4[1]}, bh1[2] = {vh4[2], vh4[3]};
                uint32_t bl0[2] = {vl4[0], vl4[1]}, bl1[2] = {vl4[2], vl4[3]};
                mma_bf16(oacc[2 * p],     apl, bh0);
                mma_bf16(oacc[2 * p],     aph, bl0);
                mma_bf16(oacc[2 * p],     aph, bh0);
                mma_bf16(oacc[2 * p + 1], apl, bh1);
                mma_bf16(oacc[2 * p + 1], aph, bl1);
                mma_bf16(oacc[2 * p + 1], aph, bh1);
            }
        }
        __syncthreads();   // all reads done before restaging the single buffer

        // stage next KV block (cp.async; overlapped across the 2 CTAs/SM)
        if (kb + 64 <= kbend) {
            const __nv_bfloat16* srcs[4] = {gKh, gKl, gVh, gVl};
#pragma unroll
            for (int i = 0; i < 32; i++) {
                int cidx = tid + 128 * i;
                int plane = cidx >> 10, rem = cidx & 1023;
                int row = rem >> 4, ch = rem & 15;
                cp_async16(uKV + plane * KPL + (row * QST + ch * 8) * 2,
                           srcs[plane] + (size_t)(kb + 64 + row) * 128 + ch * 8);
            }
            CP_COMMIT();
        }
    }

    // ---- epilogue: split(O / l) -> yh/yl planes ----
    float inv0 = __fdiv_rn(1.f, l0s);
    float inv1 = __fdiv_rn(1.f, l1s);
    const int row0 = t0 + r0 + g;
#pragma unroll
    for (int nt = 0; nt < 16; nt++) {
        int c = h * 128 + nt * 8 + tig * 2;
        uint32_t hi, lo;
        split2_pack(oacc[nt][0] * inv0, oacc[nt][1] * inv0, hi, lo);
        *(uint32_t*)(Yh + (size_t)row0 * 2048 + c) = hi;
        *(uint32_t*)(Yl + (size_t)row0 * 2048 + c) = lo;
        split2_pack(oacc[nt][2] * inv1, oacc[nt][3] * inv1, hi, lo);
        *(uint32_t*)(Yh + (size_t)(row0 + 8) * 2048 + c) = hi;
        *(uint32_t*)(Yl + (size_t)(row0 + 8) * 2048 + c) = lo;
    }
}

// ---------------------------------------------------------------------------
// Launch — multi-stream fork/join (graph-capture compatible via events).
// ---------------------------------------------------------------------------
extern "C" void kernel_launch(void* const* d_in, const int* in_sizes, int n_in,
                              void* d_out, int out_size)
{
    const float* x     = (const float*)d_in[0];
    const float* cosb  = (const float*)d_in[1];
    const float* sinb  = (const float*)d_in[2];
    const float* Wq    = (const float*)d_in[3];
    const float* Wk    = (const float*)d_in[4];
    const float* Wv    = (const float*)d_in[5];
    const float* Wproj = (const float*)d_in[6];
    float* out = (float*)d_out;

    const int T = in_sizes[0] / C_DIM;

    float *pq, *pk, *pv;
    __nv_bfloat16 *pxh, *pxl, *pyh, *pyl, *pwqh, *pwql, *pwph, *pwpl;
    __nv_bfloat16 *pQh, *pQl, *pKh, *pKl, *pVh, *pVl;
    cudaGetSymbolAddress((void**)&pq, g_q);
    cudaGetSymbolAddress((void**)&pk, g_k);
    cudaGetSymbolAddress((void**)&pv, g_v);
    cudaGetSymbolAddress((void**)&pxh, g_xh);
    cudaGetSymbolAddress((void**)&pxl, g_xl);
    cudaGetSymbolAddress((void**)&pyh, g_yh);
    cudaGetSymbolAddress((void**)&pyl, g_yl);
    cudaGetSymbolAddress((void**)&pwqh, g_wqh);
    cudaGetSymbolAddress((void**)&pwql, g_wql);
    cudaGetSymbolAddress((void**)&pwph, g_wph);
    cudaGetSymbolAddress((void**)&pwpl, g_wpl);
    cudaGetSymbolAddress((void**)&pQh, g_Qph);
    cudaGetSymbolAddress((void**)&pQl, g_Qpl);
    cudaGetSymbolAddress((void**)&pKh, g_Kph);
    cudaGetSymbolAddress((void**)&pKl, g_Kpl);
    cudaGetSymbolAddress((void**)&pVh, g_Vph);
    cudaGetSymbolAddress((void**)&pVl, g_Vpl);

    cudaFuncSetAttribute(attn_tc_kernel, cudaFuncAttributeMaxDynamicSharedMemorySize,
                         ATT_SMEM);
    cudaFuncSetAttribute(gemm_bf16x3_kernel,
                         cudaFuncAttributeMaxDynamicSharedMemorySize, GEMM_SMEM);

    dim3 blk(256);
    const int nx4 = T * 2048 / 4;

    // --- fork: 3 worker streams + origin (default) ---
    cudaStream_t s0 = 0, sA, sB, sC;
    cudaStreamCreateWithFlags(&sA, cudaStreamNonBlocking);
    cudaStreamCreateWithFlags(&sB, cudaStreamNonBlocking);
    cudaStreamCreateWithFlags(&sC, cudaStreamNonBlocking);
    cudaEvent_t evRoot, evA, evB, evC;
    cudaEventCreateWithFlags(&evRoot, cudaEventDisableTiming);
    cudaEventCreateWithFlags(&evA, cudaEventDisableTiming);
    cudaEventCreateWithFlags(&evB, cudaEventDisableTiming);
    cudaEventCreateWithFlags(&evC, cudaEventDisableTiming);

    cudaEventRecord(evRoot, s0);
    cudaStreamWaitEvent(sA, evRoot, 0);
    cudaStreamWaitEvent(sB, evRoot, 0);
    cudaStreamWaitEvent(sC, evRoot, 0);

    // --- stream A: Q-projection chain (tensor pipe) ---
    split_bf16_kernel<<<(nx4 + 255) / 256, blk, 0, sA>>>(x, pxh, pxl, nx4);
    transpose_split_kernel<<<dim3(2048 / 32, 2048 / 32), blk, 0, sA>>>(
        Wq, pwqh, pwql, 2048, 2048);
    gemm_bf16x3_kernel<<<dim3(2048 / 128, T / 128), blk, GEMM_SMEM, sA>>>(
        pxh, pxl, pwqh, pwql, pq, T, 2048, 2048);
    rope_rms_q_kernel<<<dim3(T, N_HEAD), 64, 0, sA>>>(pq, cosb, sinb, pQh, pQl, T);
    cudaEventRecord(evA, sA);

    // --- stream B: K chain (FMA pipe, frozen) ---
    sgemm_kv_kernel<<<dim3(512 / 32, T / 32), blk, 0, sB>>>(x, Wk, pk, T, 512, 2048);
    rope_rms_quant_k_kernel<<<dim3(T, N_KVH), 64, 0, sB>>>(pk, cosb, sinb, pKh, pKl, T);
    cudaEventRecord(evB, sB);

    // --- stream C: V chain (FMA pipe, frozen) + Wproj transpose ---
    sgemm_kv_kernel<<<dim3(512 / 32, T / 32), blk, 0, sC>>>(x, Wv, pv, T, 512, 2048);
    quant_v_kernel<<<dim3(T, N_KVH), 64, 0, sC>>>(pv, pVh, pVl, T);
    transpose_split_kernel<<<dim3(2048 / 32, 2048 / 32), blk, 0, sC>>>(
        Wproj, pwph, pwpl, 2048, 2048);
    cudaEventRecord(evC, sC);

    // --- join on origin, then attention + output projection ---
    cudaStreamWaitEvent(s0, evA, 0);
    cudaStreamWaitEvent(s0, evB, 0);
    cudaStreamWaitEvent(s0, evC, 0);

    attn_tc_kernel<<<dim3(T / 64, N_HEAD), 128, ATT_SMEM, s0>>>(
        pQh, pQl, pKh, pKl, pVh, pVl, pyh, pyl, T);

    gemm_bf16x3_kernel<<<dim3(2048 / 128, T / 128), blk, GEMM_SMEM, s0>>>(
        pyh, pyl, pwph, pwpl, out, T, 2048, 2048);

    cudaEventDestroy(evRoot);
    cudaEventDestroy(evA);
    cudaEventDestroy(evB);
    cudaEventDestroy(evC);
    cudaStreamDestroy(sA);
    cudaStreamDestroy(sB);
    cudaStreamDestroy(sC);
}

// round 17
// speedup vs baseline: 1.1216x; 1.0227x over previous
#include <cuda_runtime.h>
#include <cuda_bf16.h>
#include <math_constants.h>
#include <cstdint>

// ---------------------------------------------------------------------------
// Problem constants
// ---------------------------------------------------------------------------
#define T_MAX   8192
#define C_DIM   2048
#define N_HEAD  16
#define N_KVH   4
#define HDIM    128
#define WIN     1024
#define RMS_EPS 1.1920929e-07f

// ---------------------------------------------------------------------------
// Scratch (device globals; no runtime allocation allowed)
// ---------------------------------------------------------------------------
__device__ float g_q[(size_t)T_MAX * 2048];
__device__ float g_k[(size_t)T_MAX * 512];
__device__ float g_v[(size_t)T_MAX * 512];
__device__ __nv_bfloat16 g_xh[(size_t)T_MAX * 2048];
__device__ __nv_bfloat16 g_xl[(size_t)T_MAX * 2048];
__device__ __nv_bfloat16 g_yh[(size_t)T_MAX * 2048];
__device__ __nv_bfloat16 g_yl[(size_t)T_MAX * 2048];
__device__ __nv_bfloat16 g_wqh[(size_t)2048 * 2048];
__device__ __nv_bfloat16 g_wql[(size_t)2048 * 2048];
__device__ __nv_bfloat16 g_wph[(size_t)2048 * 2048];
__device__ __nv_bfloat16 g_wpl[(size_t)2048 * 2048];
__device__ __nv_bfloat16 g_Qph[(size_t)N_HEAD * T_MAX * HDIM];
__device__ __nv_bfloat16 g_Qpl[(size_t)N_HEAD * T_MAX * HDIM];
__device__ __nv_bfloat16 g_Kph[(size_t)N_KVH * T_MAX * HDIM];
__device__ __nv_bfloat16 g_Kpl[(size_t)N_KVH * T_MAX * HDIM];
__device__ __nv_bfloat16 g_Vph[(size_t)N_KVH * T_MAX * HDIM];
__device__ __nv_bfloat16 g_Vpl[(size_t)N_KVH * T_MAX * HDIM];

// ---------------------------------------------------------------------------
// PTX helpers
// ---------------------------------------------------------------------------
__device__ __forceinline__ void mma_bf16(float* d,
                                         const uint32_t* a, const uint32_t* b) {
    asm volatile(
        "mma.sync.aligned.m16n8k16.row.col.f32.bf16.bf16.f32 "
        "{%0,%1,%2,%3}, {%4,%5,%6,%7}, {%8,%9}, {%0,%1,%2,%3};"
        : "+f"(d[0]), "+f"(d[1]), "+f"(d[2]), "+f"(d[3])
        : "r"(a[0]), "r"(a[1]), "r"(a[2]), "r"(a[3]),
          "r"(b[0]), "r"(b[1]));
}
__device__ __forceinline__ void ldsm_x4(uint32_t* r, uint32_t saddr) {
    asm volatile(
        "ldmatrix.sync.aligned.m8n8.x4.shared.b16 {%0,%1,%2,%3}, [%4];"
        : "=r"(r[0]), "=r"(r[1]), "=r"(r[2]), "=r"(r[3]) : "r"(saddr));
}
__device__ __forceinline__ void ldsm_x4_trans(uint32_t* r, uint32_t saddr) {
    asm volatile(
        "ldmatrix.sync.aligned.m8n8.x4.trans.shared.b16 {%0,%1,%2,%3}, [%4];"
        : "=r"(r[0]), "=r"(r[1]), "=r"(r[2]), "=r"(r[3]) : "r"(saddr));
}
__device__ __forceinline__ void cp_async16(uint32_t s, const void* g) {
    asm volatile("cp.async.cg.shared.global [%0], [%1], 16;" :: "r"(s), "l"(g));
}
#define CP_COMMIT() asm volatile("cp.async.commit_group;" ::: "memory")
#define CP_WAIT0()  asm volatile("cp.async.wait_group 0;" ::: "memory")

__device__ __forceinline__ uint32_t smem_to_u32(const void* p) {
    uint32_t a;
    asm("{ .reg .u64 t; cvta.to.shared.u64 t, %1; cvt.u32.u64 %0, t; }"
        : "=r"(a) : "l"(p));
    return a;
}
__device__ __forceinline__ uint32_t pack_bf16(__nv_bfloat16 a, __nv_bfloat16 b) {
    return (uint32_t)__bfloat16_as_ushort(a) |
           ((uint32_t)__bfloat16_as_ushort(b) << 16);
}
__device__ __forceinline__ void split2_pack(float x, float y,
                                            uint32_t& hi, uint32_t& lo) {
    __nv_bfloat16 hx = __float2bfloat16(x);
    __nv_bfloat16 hy = __float2bfloat16(y);
    __nv_bfloat16 lx = __float2bfloat16(__fsub_rn(x, __bfloat162float(hx)));
    __nv_bfloat16 ly = __float2bfloat16(__fsub_rn(y, __bfloat162float(hy)));
    hi = pack_bf16(hx, hy);
    lo = pack_bf16(lx, ly);
}
__device__ __forceinline__ void split1(float x, __nv_bfloat16& h, __nv_bfloat16& l) {
    h = __float2bfloat16(x);
    l = __float2bfloat16(__fsub_rn(x, __bfloat162float(h)));
}

// ---------------------------------------------------------------------------
// fp32 -> (hi, lo) bf16 split, elementwise. n4 = n/4.
// ---------------------------------------------------------------------------
__global__ void split_bf16_kernel(const float* __restrict__ X,
                                  __nv_bfloat16* __restrict__ H,
                                  __nv_bfloat16* __restrict__ L, int n4)
{
    int i = blockIdx.x * blockDim.x + threadIdx.x;
    if (i >= n4) return;
    float4 v = ((const float4*)X)[i];
    float xs[4] = {v.x, v.y, v.z, v.w};
    union { __nv_bfloat16 b[4]; uint2 u; } ph, pl;
#pragma unroll
    for (int j = 0; j < 4; j++) split1(xs[j], ph.b[j], pl.b[j]);
    *(uint2*)(H + (size_t)i * 4) = ph.u;
    *(uint2*)(L + (size_t)i * 4) = pl.u;
}

// ---------------------------------------------------------------------------
// W [K, N] fp32 -> Wt hi/lo bf16 [N, K] (transpose + split). 32x32 tiles.
// ---------------------------------------------------------------------------
__global__ void transpose_split_kernel(const float* __restrict__ W,
                                       __nv_bfloat16* __restrict__ Th,
                                       __nv_bfloat16* __restrict__ Tl,
                                       int K, int N)
{
    __shared__ float tile[32][33];
    int k0 = blockIdx.y * 32, n0 = blockIdx.x * 32;
    int tx = threadIdx.x & 31, ty = threadIdx.x >> 5;
#pragma unroll
    for (int r = ty; r < 32; r += 8)
        tile[r][tx] = W[(size_t)(k0 + r) * N + n0 + tx];
    __syncthreads();
#pragma unroll
    for (int r = ty; r < 32; r += 8) {
        __nv_bfloat16 h, l;
        split1(tile[tx][r], h, l);
        Th[(size_t)(n0 + r) * K + k0 + tx] = h;
        Tl[(size_t)(n0 + r) * K + k0 + tx] = l;
    }
}

// ---------------------------------------------------------------------------
// bf16x3 tensor-core GEMM (unchanged).
// ---------------------------------------------------------------------------
#define GST 40
#define GPL (128 * GST * 2)
#define GSTG (4 * GPL)
#define GEMM_SMEM (2 * GSTG)

__global__ __launch_bounds__(256, 2) void gemm_bf16x3_kernel(
    const __nv_bfloat16* __restrict__ Ah, const __nv_bfloat16* __restrict__ Al,
    const __nv_bfloat16* __restrict__ Bh, const __nv_bfloat16* __restrict__ Bl,
    float* __restrict__ C, int M, int N, int K)
{
    extern __shared__ __nv_bfloat16 gsm[];
    const uint32_t sbu = smem_to_u32(gsm);

    const int tid  = threadIdx.x;
    const int lane = tid & 31;
    const int wid  = tid >> 5;
    const int wm   = wid & 1;
    const int wn   = wid >> 1;

    const __nv_bfloat16* gAh = Ah + (size_t)blockIdx.y * 128 * K;
    const __nv_bfloat16* gAl = Al + (size_t)blockIdx.y * 128 * K;
    const __nv_bfloat16* gBh = Bh + (size_t)blockIdx.x * 128 * K;
    const __nv_bfloat16* gBl = Bl + (size_t)blockIdx.x * 128 * K;

    const int srow0 = tid >> 2, sc0 = (tid & 3) * 8;
    const int srow1 = (tid + 256) >> 2, sc1 = ((tid + 256) & 3) * 8;

    float acc[4][4][4];
#pragma unroll
    for (int mt = 0; mt < 4; mt++)
#pragma unroll
        for (int nt = 0; nt < 4; nt++)
#pragma unroll
            for (int e = 0; e < 4; e++) acc[mt][nt][e] = 0.f;

    const uint32_t aRow = (lane & 15);
    const uint32_t aCol = (lane & 16) ? 8 : 0;
    const uint32_t bRow = (lane & 7) + ((lane & 16) >> 1);
    const uint32_t bCol = (lane & 8);

    const int nIter = K / 32;

    {
        uint32_t base = sbu;
        size_t go0 = (size_t)srow0 * K + sc0;
        size_t go1 = (size_t)srow1 * K + sc1;
        uint32_t so0 = base + (srow0 * GST + sc0) * 2;
        uint32_t so1 = base + (srow1 * GST + sc1) * 2;
        cp_async16(so0,           gAh + go0);
        cp_async16(so0 + GPL,     gAl + go0);
        cp_async16(so0 + 2 * GPL, gBh + go0);
        cp_async16(so0 + 3 * GPL, gBl + go0);
        cp_async16(so1,           gAh + go1);
        cp_async16(so1 + GPL,     gAl + go1);
        cp_async16(so1 + 2 * GPL, gBh + go1);
        cp_async16(so1 + 3 * GPL, gBl + go1);
        CP_COMMIT();
    }

    int cur = 0;
    for (int it = 0; it < nIter; it++) {
        CP_WAIT0();
        __syncthreads();

        if (it + 1 < nIter) {
            int k0n = (it + 1) * 32;
            uint32_t base = sbu + (cur ^ 1) * GSTG;
            size_t go0 = (size_t)srow0 * K + k0n + sc0;
            size_t go1 = (size_t)srow1 * K + k0n + sc1;
            uint32_t so0 = base + (srow0 * GST + sc0) * 2;
            uint32_t so1 = base + (srow1 * GST + sc1) * 2;
            cp_async16(so0,           gAh + go0);
            cp_async16(so0 + GPL,     gAl + go0);
            cp_async16(so0 + 2 * GPL, gBh + go0);
            cp_async16(so0 + 3 * GPL, gBl + go0);
            cp_async16(so1,           gAh + go1);
            cp_async16(so1 + GPL,     gAl + go1);
            cp_async16(so1 + 2 * GPL, gBh + go1);
            cp_async16(so1 + 3 * GPL, gBl + go1);
            CP_COMMIT();
        }

        const uint32_t bA = sbu + cur * GSTG;
        const uint32_t bAl_ = bA + GPL;
        const uint32_t bB = bA + 2 * GPL;
        const uint32_t bBl_ = bA + 3 * GPL;

#pragma unroll
        for (int ks = 0; ks < 2; ks++) {
            const int ko = ks * 16;
            uint32_t bh[4][2], bl[4][2];
#pragma unroll
            for (int p = 0; p < 2; p++) {
                uint32_t roff = ((wn * 32 + p * 16 + bRow) * GST + ko + bCol) * 2;
                uint32_t t4[4];
                ldsm_x4(t4, bB + roff);
                bh[2 * p][0] = t4[0]; bh[2 * p][1] = t4[1];
                bh[2 * p + 1][0] = t4[2]; bh[2 * p + 1][1] = t4[3];
                ldsm_x4(t4, bBl_ + roff);
                bl[2 * p][0] = t4[0]; bl[2 * p][1] = t4[1];
                bl[2 * p + 1][0] = t4[2]; bl[2 * p + 1][1] = t4[3];
            }
#pragma unroll
            for (int mt = 0; mt < 4; mt++) {
                uint32_t aoff = ((wm * 64 + mt * 16 + aRow) * GST + ko + aCol) * 2;
                uint32_t ah[4], al[4];
                ldsm_x4(ah, bA + aoff);
                ldsm_x4(al, bAl_ + aoff);
#pragma unroll
                for (int nt = 0; nt < 4; nt++) {
                    mma_bf16(acc[mt][nt], al, bh[nt]);
                    mma_bf16(acc[mt][nt], ah, bl[nt]);
                    mma_bf16(acc[mt][nt], ah, bh[nt]);
                }
            }
        }
        cur ^= 1;
    }

    const int g2 = lane >> 2, tig2 = lane & 3;
#pragma unroll
    for (int mt = 0; mt < 4; mt++) {
#pragma unroll
        for (int nt = 0; nt < 4; nt++) {
            int r = blockIdx.y * 128 + wm * 64 + mt * 16 + g2;
            int c = blockIdx.x * 128 + wn * 32 + nt * 8 + tig2 * 2;
            *(float2*)(C + (size_t)r * N + c) =
                make_float2(acc[mt][nt][0], acc[mt][nt][1]);
            *(float2*)(C + (size_t)(r + 8) * N + c) =
                make_float2(acc[mt][nt][2], acc[mt][nt][3]);
        }
    }
}

// ---------------------------------------------------------------------------
// K/V projection SGEMM — *** ARITHMETIC FROZEN *** (Round 14 WIN version).
// ---------------------------------------------------------------------------
#define KVST 36

__global__ __launch_bounds__(256) void sgemm_kv_kernel(
    const float* __restrict__ A, const float* __restrict__ B,
    float* __restrict__ C, int M, int N, int K)
{
    __shared__ float As[2][32][KVST];
    __shared__ float Bs[2][32][KVST];

    const int tid = threadIdx.x;
    const int tx  = tid & 31;
    const int ty  = tid >> 5;
    const int bx  = blockIdx.x;
    const int by  = blockIdx.y;

    const float* Ab = A + (size_t)(by * 32) * K;
    const float* Bb = B + (size_t)(bx * 32);

    const int am = tid >> 3;
    const int ak = (tid & 7) << 2;
    const int bk = tid >> 3;
    const int bn = (tid & 7) << 2;

    float part[4][16];
#pragma unroll
    for (int r = 0; r < 4; r++)
#pragma unroll
        for (int j = 0; j < 16; j++) part[r][j] = 0.f;

    const int nIter = K / 32;
    float4 a_reg = *(const float4*)(Ab + (size_t)am * K + ak);
    float4 b_reg = *(const float4*)(Bb + (size_t)bk * N + bn);

    int buf = 0;
    for (int it = 0; it < nIter; it++) {
        As[buf][ak + 0][am] = a_reg.x;
        As[buf][ak + 1][am] = a_reg.y;
        As[buf][ak + 2][am] = a_reg.z;
        As[buf][ak + 3][am] = a_reg.w;
        *(float4*)&Bs[buf][bk][bn] = b_reg;
        __syncthreads();

        if (it + 1 < nIter) {
            int k0n = (it + 1) * 32;
            a_reg = *(const float4*)(Ab + (size_t)am * K + k0n + ak);
            b_reg = *(const float4*)(Bb + (size_t)(k0n + bk) * N + bn);
        }

#pragma unroll
        for (int j = 0; j < 16; j++) {
            float4 a0 = *(const float4*)&As[buf][j][ty * 4];
            float  b0 = Bs[buf][j][tx];
            part[0][j] = __fmaf_rn(a0.x, b0, part[0][j]);
            part[1][j] = __fmaf_rn(a0.y, b0, part[1][j]);
            part[2][j] = __fmaf_rn(a0.z, b0, part[2][j]);
            part[3][j] = __fmaf_rn(a0.w, b0, part[3][j]);
            float4 a1 = *(const float4*)&As[buf][j + 16][ty * 4];
            float  b1 = Bs[buf][j + 16][tx];
            part[0][j] = __fmaf_rn(a1.x, b1, part[0][j]);
            part[1][j] = __fmaf_rn(a1.y, b1, part[1][j]);
            part[2][j] = __fmaf_rn(a1.z, b1, part[2][j]);
            part[3][j] = __fmaf_rn(a1.w, b1, part[3][j]);
        }
        buf ^= 1;
    }

#pragma unroll
    for (int r = 0; r < 4; r++) {
        float w[4];
#pragma unroll
        for (int l = 0; l < 4; l++)
            w[l] = __fadd_rn(__fadd_rn(part[r][l],     part[r][4 + l]),
                             __fadd_rn(part[r][8 + l], part[r][12 + l]));
        float res = __fadd_rn(__fadd_rn(w[0], w[1]), __fadd_rn(w[2], w[3]));
        C[(size_t)(by * 32 + ty * 4 + r) * N + bx * 32 + tx] = res;
    }
}

__device__ __forceinline__ float rsqrt_rn(float x) {
    return __fdiv_rn(1.0f, __fsqrt_rn(x));
}

// ---------------------------------------------------------------------------
// RoPE + RMS for Q -> bf16 hi/lo planes.
// ---------------------------------------------------------------------------
__global__ void rope_rms_q_kernel(
    const float* __restrict__ X, const float* __restrict__ cosb,
    const float* __restrict__ sinb,
    __nv_bfloat16* __restrict__ Qh, __nv_bfloat16* __restrict__ Ql, int T)
{
    const int t = blockIdx.x, h = blockIdx.y, d = threadIdx.x;
    const float* row = X + (size_t)t * 2048 + h * 128;
    float x1 = row[d], x2 = row[d + 64];
    float c = cosb[t * 64 + d], s = sinb[t * 64 + d];
    float o1 = __fadd_rn(__fmul_rn(x1, c), __fmul_rn(x2, s));
    float o2 = __fsub_rn(__fmul_rn(x2, c), __fmul_rn(x1, s));

    float ss = __fadd_rn(__fmul_rn(o1, o1), __fmul_rn(o2, o2));
#pragma unroll
    for (int o = 16; o > 0; o >>= 1) ss += __shfl_down_sync(0xffffffffu, ss, o);
    __shared__ float sh[2];
    if ((d & 31) == 0) sh[d >> 5] = ss;
    __syncthreads();
    float ms = __fmul_rn(__fadd_rn(sh[0], sh[1]), 0.0078125f);
    float r = rsqrt_rn(__fadd_rn(ms, RMS_EPS));

    size_t base = ((size_t)h * T + t) * 128;
    __nv_bfloat16 hh, ll;
    split1(__fmul_rn(o1, r), hh, ll);
    Qh[base + d] = hh;  Ql[base + d] = ll;
    split1(__fmul_rn(o2, r), hh, ll);
    Qh[base + d + 64] = hh;  Ql[base + d + 64] = ll;
}

// ---------------------------------------------------------------------------
// RoPE + RMS + quant for K — frozen fp32 chain, then split to planes.
// ---------------------------------------------------------------------------
__global__ void rope_rms_quant_k_kernel(
    const float* __restrict__ X, const float* __restrict__ cosb,
    const float* __restrict__ sinb,
    __nv_bfloat16* __restrict__ Kh, __nv_bfloat16* __restrict__ Kl, int T)
{
    const int t = blockIdx.x, h = blockIdx.y, d = threadIdx.x;
    const float* row = X + (size_t)t * 512 + h * 128;
    float x1 = row[d], x2 = row[d + 64];
    float c = cosb[t * 64 + d], s = sinb[t * 64 + d];
    float o1 = __fadd_rn(__fmul_rn(x1, c), __fmul_rn(x2, s));
    float o2 = __fsub_rn(__fmul_rn(x2, c), __fmul_rn(x1, s));

    __shared__ float sh[4];
    float ss = __fadd_rn(__fmul_rn(o1, o1), __fmul_rn(o2, o2));
#pragma unroll
    for (int o = 16; o > 0; o >>= 1) ss += __shfl_down_sync(0xffffffffu, ss, o);
    if ((d & 31) == 0) sh[d >> 5] = ss;
    __syncthreads();
    float ms = __fmul_rn(__fadd_rn(sh[0], sh[1]), 0.0078125f);
    float r = rsqrt_rn(__fadd_rn(ms, RMS_EPS));
    float k1 = __fmul_rn(o1, r), k2 = __fmul_rn(o2, r);

    float m = fmaxf(fabsf(k1), fabsf(k2));
#pragma unroll
    for (int o = 16; o > 0; o >>= 1) m = fmaxf(m, __shfl_down_sync(0xffffffffu, m, o));
    if ((d & 31) == 0) sh[2 + (d >> 5)] = m;
    __syncthreads();
    float sq = fmaxf(__fdiv_rn(fmaxf(sh[2], sh[3]), 3.0f), 1e-8f);
    float q1 = __fmul_rn(fminf(fmaxf(rintf(__fdiv_rn(k1, sq)), -3.f), 3.f), sq);
    float q2 = __fmul_rn(fminf(fmaxf(rintf(__fdiv_rn(k2, sq)), -3.f), 3.f), sq);

    size_t base = ((size_t)h * T + t) * 128;
    __nv_bfloat16 hh, ll;
    split1(q1, hh, ll);
    Kh[base + d] = hh;  Kl[base + d] = ll;
    split1(q2, hh, ll);
    Kh[base + d + 64] = hh;  Kl[base + d + 64] = ll;
}

// ---------------------------------------------------------------------------
// Quant V — frozen fp32 chain, then split to planes.
// ---------------------------------------------------------------------------
__global__ void quant_v_kernel(
    const float* __restrict__ X,
    __nv_bfloat16* __restrict__ Vh, __nv_bfloat16* __restrict__ Vl, int T)
{
    const int t = blockIdx.x, h = blockIdx.y, d = threadIdx.x;
    const float* row = X + (size_t)t * 512 + h * 128;
    float v1 = row[d], v2 = row[d + 64];

    __shared__ float sh[2];
    float m = fmaxf(fabsf(v1), fabsf(v2));
#pragma unroll
    for (int o = 16; o > 0; o >>= 1) m = fmaxf(m, __shfl_down_sync(0xffffffffu, m, o));
    if ((d & 31) == 0) sh[d >> 5] = m;
    __syncthreads();
    float sq = fmaxf(__fdiv_rn(fmaxf(sh[0], sh[1]), 3.0f), 1e-8f);
    float q1 = __fmul_rn(fminf(fmaxf(rintf(__fdiv_rn(v1, sq)), -3.f), 3.f), sq);
    float q2 = __fmul_rn(fminf(fmaxf(rintf(__fdiv_rn(v2, sq)), -3.f), 3.f), sq);

    size_t base = ((size_t)h * T + t) * 128;
    __nv_bfloat16 hh, ll;
    split1(q1, hh, ll);
    Vh[base + d] = hh;  Vl[base + d] = ll;
    split1(q2, hh, ll);
    Vh[base + d + 64] = hh;  Vl[base + d + 64] = ll;
}

// ---------------------------------------------------------------------------
// Tensor-core flash attention v5: v4 + register-resident Q fragments (hoisted
// out of the key loop) + whole-warp fast-path masking for interior blocks.
// Per-row arithmetic identical (bit-exact output).
// ---------------------------------------------------------------------------
#define QST 136
#define QPL2 (64 * QST * 2)
#define KPL  (64 * QST * 2)
#define ATT_SMEM (2 * QPL2 + 4 * KPL)    // 104448 -> 2 CTAs/SM

__global__ __launch_bounds__(128, 2) void attn_tc_kernel(
    const __nv_bfloat16* __restrict__ Qh, const __nv_bfloat16* __restrict__ Ql,
    const __nv_bfloat16* __restrict__ Kh, const __nv_bfloat16* __restrict__ Kl,
    const __nv_bfloat16* __restrict__ Vh, const __nv_bfloat16* __restrict__ Vl,
    __nv_bfloat16* __restrict__ Yh, __nv_bfloat16* __restrict__ Yl, int T)
{
    extern __shared__ __nv_bfloat16 sm[];
    const uint32_t uQ  = smem_to_u32(sm);
    const uint32_t uQl = uQ + QPL2;
    const uint32_t uKV = uQ + 2 * QPL2;
    const uint32_t uKh_ = uKV;
    const uint32_t uKl_ = uKV + KPL;
    const uint32_t uVh_ = uKV + 2 * KPL;
    const uint32_t uVl_ = uKV + 3 * KPL;

    const int tid  = threadIdx.x;
    const int lane = tid & 31;
    const int wr   = tid >> 5;
    const int g    = lane >> 2;
    const int tig  = lane & 3;
    const int h    = blockIdx.y;
    const int t0   = blockIdx.x << 6;
    const int hk   = h >> 2;
    const int r0   = wr * 16;

    const uint32_t aRow = (lane & 15);
    const uint32_t aCol = (lane & 16) ? 8 : 0;
    const uint32_t bRow = (lane & 7) + ((lane & 16) >> 1);
    const uint32_t bCol = (lane & 8);
    const uint32_t vKey = (lane & 7) + ((lane >> 3) & 1) * 8;
    const uint32_t vDim = (lane >> 4) * 8;

    const __nv_bfloat16* gQh = Qh + ((size_t)h * T + t0) * 128;
    const __nv_bfloat16* gQl = Ql + ((size_t)h * T + t0) * 128;
    const __nv_bfloat16* gKh = Kh + (size_t)hk * T * 128;
    const __nv_bfloat16* gKl = Kl + (size_t)hk * T * 128;
    const __nv_bfloat16* gVh = Vh + (size_t)hk * T * 128;
    const __nv_bfloat16* gVl = Vl + (size_t)hk * T * 128;
    const float scale = 0.08838834764831845f;

    int kb0 = t0 - WIN; if (kb0 < 0) kb0 = 0;
    const int kbend = t0;

    // ---- prologue: stage Q + first KV block ----
#pragma unroll
    for (int i = 0; i < 16; i++) {
        int cidx = tid + 128 * i;
        int plane = cidx >> 10, rem = cidx & 1023;
        int row = rem >> 4, ch = rem & 15;
        const __nv_bfloat16* src = (plane ? gQl : gQh) + (size_t)row * 128 + ch * 8;
        cp_async16(uQ + plane * QPL2 + (row * QST + ch * 8) * 2, src);
    }
    {
        const __nv_bfloat16* srcs[4] = {gKh, gKl, gVh, gVl};
#pragma unroll
        for (int i = 0; i < 32; i++) {
            int cidx = tid + 128 * i;
            int plane = cidx >> 10, rem = cidx & 1023;
            int row = rem >> 4, ch = rem & 15;
            cp_async16(uKV + plane * KPL + (row * QST + ch * 8) * 2,
                       srcs[plane] + (size_t)(kb0 + row) * 128 + ch * 8);
        }
    }
    CP_COMMIT();
    CP_WAIT0();
    __syncthreads();

    // ---- hoist Q fragments into registers (loop-invariant) ----
    uint32_t qfh[8][4], qfl[8][4];
#pragma unroll
    for (int kt = 0; kt < 8; kt++) {
        uint32_t qoff = ((r0 + aRow) * QST + kt * 16 + aCol) * 2;
        ldsm_x4(qfh[kt], uQ + qoff);
        ldsm_x4(qfl[kt], uQl + qoff);
    }

    float m0 = -CUDART_INF_F, m1 = -CUDART_INF_F, l0s = 0.f, l1s = 0.f;
    float oacc[16][4];
#pragma unroll
    for (int nt = 0; nt < 16; nt++)
#pragma unroll
        for (int e = 0; e < 4; e++) oacc[nt][e] = 0.f;

    for (int kb = kb0; kb <= kbend; kb += 64) {
        // ---- S = Q @ K^T (bf16x3), Q fragments from registers ----
        float sacc[8][4];
#pragma unroll
        for (int nt = 0; nt < 8; nt++)
#pragma unroll
            for (int e = 0; e < 4; e++) sacc[nt][e] = 0.f;

#pragma unroll
        for (int kt = 0; kt < 8; kt++) {
            const int kc = kt * 16;
            uint32_t kfh[8][2], kfl[8][2];
#pragma unroll
            for (int p = 0; p < 4; p++) {
                uint32_t koff = ((p * 16 + bRow) * QST + kc + bCol) * 2;
                uint32_t t4[4];
                ldsm_x4(t4, uKh_ + koff);
                kfh[2 * p][0] = t4[0]; kfh[2 * p][1] = t4[1];
                kfh[2 * p + 1][0] = t4[2]; kfh[2 * p + 1][1] = t4[3];
                ldsm_x4(t4, uKl_ + koff);
                kfl[2 * p][0] = t4[0]; kfl[2 * p][1] = t4[1];
                kfl[2 * p + 1][0] = t4[2]; kfl[2 * p + 1][1] = t4[3];
            }
#pragma unroll
            for (int nt = 0; nt < 8; nt++) {
                mma_bf16(sacc[nt], qfl[kt], kfh[nt]);
                mma_bf16(sacc[nt], qfh[kt], kfl[nt]);
                mma_bf16(sacc[nt], qfh[kt], kfh[nt]);
            }
        }

        // ---- mask + scale (whole-warp fast path for interior blocks) ----
        const int row0 = t0 + r0 + g;
        const int row1 = row0 + 8;
        float rmax0 = -CUDART_INF_F, rmax1 = -CUDART_INF_F;
        const bool warp_full = (kb + 63 <= t0 + r0) && (kb + WIN > t0 + r0 + 15);
        if (warp_full) {
#pragma unroll
            for (int nt = 0; nt < 8; nt++) {
#pragma unroll
                for (int e = 0; e < 4; e++) {
                    float s = sacc[nt][e] * scale;   // identical value to masked path
                    sacc[nt][e] = s;
                    if (e < 2) rmax0 = fmaxf(rmax0, s);
                    else       rmax1 = fmaxf(rmax1, s);
                }
            }
        } else {
#pragma unroll
            for (int nt = 0; nt < 8; nt++) {
                int c0 = kb + nt * 8 + tig * 2;
#pragma unroll
                for (int e = 0; e < 4; e++) {
                    int col = c0 + (e & 1);
                    int row = (e < 2) ? row0 : row1;
                    bool valid = (col <= row) && (col + WIN > row);
                    float s = valid ? sacc[nt][e] * scale : -CUDART_INF_F;
                    sacc[nt][e] = s;
                    if (e < 2) rmax0 = fmaxf(rmax0, s);
                    else       rmax1 = fmaxf(rmax1, s);
                }
            }
        }
        rmax0 = fmaxf(rmax0, __shfl_xor_sync(0xffffffffu, rmax0, 1));
        rmax0 = fmaxf(rmax0, __shfl_xor_sync(0xffffffffu, rmax0, 2));
        rmax1 = fmaxf(rmax1, __shfl_xor_sync(0xffffffffu, rmax1, 1));
        rmax1 = fmaxf(rmax1, __shfl_xor_sync(0xffffffffu, rmax1, 2));

        float mn0 = fmaxf(m0, rmax0), mn1 = fmaxf(m1, rmax1);
        float mm0 = (mn0 == -CUDART_INF_F) ? 0.f : mn0;
        float mm1 = (mn1 == -CUDART_INF_F) ? 0.f : mn1;
        float c0 = __expf(m0 - mm0);
        float c1 = __expf(m1 - mm1);
        if (m0 == -CUDART_INF_F) c0 = (mn0 == -CUDART_INF_F) ? 1.f : 0.f;
        if (m1 == -CUDART_INF_F) c1 = (mn1 == -CUDART_INF_F) ? 1.f : 0.f;

        float sum0 = 0.f, sum1 = 0.f;
#pragma unroll
        for (int nt = 0; nt < 8; nt++) {
#pragma unroll
            for (int e = 0; e < 4; e++) {
                float s = sacc[nt][e];
                float p = (s == -CUDART_INF_F) ? 0.f
                         : __expf(s - ((e < 2) ? mm0 : mm1));
                sacc[nt][e] = p;
                if (e < 2) sum0 += p; else sum1 += p;
            }
        }
        sum0 += __shfl_xor_sync(0xffffffffu, sum0, 1);
        sum0 += __shfl_xor_sync(0xffffffffu, sum0, 2);
        sum1 += __shfl_xor_sync(0xffffffffu, sum1, 1);
        sum1 += __shfl_xor_sync(0xffffffffu, sum1, 2);

        l0s = l0s * c0 + sum0;  m0 = mn0;
        l1s = l1s * c1 + sum1;  m1 = mn1;

#pragma unroll
        for (int nt = 0; nt < 16; nt++) {
            oacc[nt][0] *= c0; oacc[nt][1] *= c0;
            oacc[nt][2] *= c1; oacc[nt][3] *= c1;
        }

        // ---- O += P @ V (bf16x3); V fragments via ldmatrix.trans ----
#pragma unroll
        for (int kt = 0; kt < 4; kt++) {
            uint32_t aph[4], apl[4];
            split2_pack(sacc[2 * kt][0],     sacc[2 * kt][1],     aph[0], apl[0]);
            split2_pack(sacc[2 * kt][2],     sacc[2 * kt][3],     aph[1], apl[1]);
            split2_pack(sacc[2 * kt + 1][0], sacc[2 * kt + 1][1], aph[2], apl[2]);
            split2_pack(sacc[2 * kt + 1][2], sacc[2 * kt + 1][3], aph[3], apl[3]);
            const int kc = kt * 16;
#pragma unroll
            for (int p = 0; p < 8; p++) {
                uint32_t voff = ((kc + vKey) * QST + p * 16 + vDim) * 2;
                uint32_t vh4[4], vl4[4];
                ldsm_x4_trans(vh4, uVh_ + voff);
                ldsm_x4_trans(vl4, uVl_ + voff);
                uint32_t bh0[2] = {vh4[0], vh4[1]}, bh1[2] = {vh4[2], vh4[3]};
                uint32_t bl0[2] = {vl4[0], vl4[1]}, bl1[2] = {vl4[2], vl4[3]};
                mma_bf16(oacc[2 * p],     apl, bh0);
                mma_bf16(oacc[2 * p],     aph, bl0);
                mma_bf16(oacc[2 * p],     aph, bh0);
                mma_bf16(oacc[2 * p + 1], apl, bh1);
                mma_bf16(oacc[2 * p + 1], aph, bl1);
                mma_bf16(oacc[2 * p + 1], aph, bh1);
            }
        }
        __syncthreads();   // all KV reads done before restaging

        if (kb + 64 <= kbend) {
            const __nv_bfloat16* srcs[4] = {gKh, gKl, gVh, gVl};
#pragma unroll
            for (int i = 0; i < 32; i++) {
                int cidx = tid + 128 * i;
                int plane = cidx >> 10, rem = cidx & 1023;
                int row = rem >> 4, ch = rem & 15;
                cp_async16(uKV + plane * KPL + (row * QST + ch * 8) * 2,
                           srcs[plane] + (size_t)(kb + 64 + row) * 128 + ch * 8);
            }
            CP_COMMIT();
            CP_WAIT0();
            __syncthreads();
        }
    }

    // ---- epilogue: split(O / l) -> yh/yl planes ----
    float inv0 = __fdiv_rn(1.f, l0s);
    float inv1 = __fdiv_rn(1.f, l1s);
    const int row0 = t0 + r0 + g;
#pragma unroll
    for (int nt = 0; nt < 16; nt++) {
        int c = h * 128 + nt * 8 + tig * 2;
        uint32_t hi, lo;
        split2_pack(oacc[nt][0] * inv0, oacc[nt][1] * inv0, hi, lo);
        *(uint32_t*)(Yh + (size_t)row0 * 2048 + c) = hi;
        *(uint32_t*)(Yl + (size_t)row0 * 2048 + c) = lo;
        split2_pack(oacc[nt][2] * inv1, oacc[nt][3] * inv1, hi, lo);
        *(uint32_t*)(Yh + (size_t)(row0 + 8) * 2048 + c) = hi;
        *(uint32_t*)(Yl + (size_t)(row0 + 8) * 2048 + c) = lo;
    }
}

// ---------------------------------------------------------------------------
// Launch — multi-stream fork/join.
// ---------------------------------------------------------------------------
extern "C" void kernel_launch(void* const* d_in, const int* in_sizes, int n_in,
                              void* d_out, int out_size)
{
    const float* x     = (const float*)d_in[0];
    const float* cosb  = (const float*)d_in[1];
    const float* sinb  = (const float*)d_in[2];
    const float* Wq    = (const float*)d_in[3];
    const float* Wk    = (const float*)d_in[4];
    const float* Wv    = (const float*)d_in[5];
    const float* Wproj = (const float*)d_in[6];
    float* out = (float*)d_out;

    const int T = in_sizes[0] / C_DIM;

    float *pq, *pk, *pv;
    __nv_bfloat16 *pxh, *pxl, *pyh, *pyl, *pwqh, *pwql, *pwph, *pwpl;
    __nv_bfloat16 *pQh, *pQl, *pKh, *pKl, *pVh, *pVl;
    cudaGetSymbolAddress((void**)&pq, g_q);
    cudaGetSymbolAddress((void**)&pk, g_k);
    cudaGetSymbolAddress((void**)&pv, g_v);
    cudaGetSymbolAddress((void**)&pxh, g_xh);
    cudaGetSymbolAddress((void**)&pxl, g_xl);
    cudaGetSymbolAddress((void**)&pyh, g_yh);
    cudaGetSymbolAddress((void**)&pyl, g_yl);
    cudaGetSymbolAddress((void**)&pwqh, g_wqh);
    cudaGetSymbolAddress((void**)&pwql, g_wql);
    cudaGetSymbolAddress((void**)&pwph, g_wph);
    cudaGetSymbolAddress((void**)&pwpl, g_wpl);
    cudaGetSymbolAddress((void**)&pQh, g_Qph);
    cudaGetSymbolAddress((void**)&pQl, g_Qpl);
    cudaGetSymbolAddress((void**)&pKh, g_Kph);
    cudaGetSymbolAddress((void**)&pKl, g_Kpl);
    cudaGetSymbolAddress((void**)&pVh, g_Vph);
    cudaGetSymbolAddress((void**)&pVl, g_Vpl);

    cudaFuncSetAttribute(attn_tc_kernel, cudaFuncAttributeMaxDynamicSharedMemorySize,
                         ATT_SMEM);
    cudaFuncSetAttribute(gemm_bf16x3_kernel,
                         cudaFuncAttributeMaxDynamicSharedMemorySize, GEMM_SMEM);

    dim3 blk(256);
    const int nx4 = T * 2048 / 4;

    cudaStream_t s0 = 0, sA, sB, sC;
    cudaStreamCreateWithFlags(&sA, cudaStreamNonBlocking);
    cudaStreamCreateWithFlags(&sB, cudaStreamNonBlocking);
    cudaStreamCreateWithFlags(&sC, cudaStreamNonBlocking);
    cudaEvent_t evRoot, evA, evB, evC;
    cudaEventCreateWithFlags(&evRoot, cudaEventDisableTiming);
    cudaEventCreateWithFlags(&evA, cudaEventDisableTiming);
    cudaEventCreateWithFlags(&evB, cudaEventDisableTiming);
    cudaEventCreateWithFlags(&evC, cudaEventDisableTiming);

    cudaEventRecord(evRoot, s0);
    cudaStreamWaitEvent(sA, evRoot, 0);
    cudaStreamWaitEvent(sB, evRoot, 0);
    cudaStreamWaitEvent(sC, evRoot, 0);

    // --- stream A: Q-projection chain (tensor pipe) ---
    split_bf16_kernel<<<(nx4 + 255) / 256, blk, 0, sA>>>(x, pxh, pxl, nx4);
    transpose_split_kernel<<<dim3(2048 / 32, 2048 / 32), blk, 0, sA>>>(
        Wq, pwqh, pwql, 2048, 2048);
    gemm_bf16x3_kernel<<<dim3(2048 / 128, T / 128), blk, GEMM_SMEM, sA>>>(
        pxh, pxl, pwqh, pwql, pq, T, 2048, 2048);
    rope_rms_q_kernel<<<dim3(T, N_HEAD), 64, 0, sA>>>(pq, cosb, sinb, pQh, pQl, T);
    cudaEventRecord(evA, sA);

    // --- stream B: K chain (FMA pipe, frozen) ---
    sgemm_kv_kernel<<<dim3(512 / 32, T / 32), blk, 0, sB>>>(x, Wk, pk, T, 512, 2048);
    rope_rms_quant_k_kernel<<<dim3(T, N_KVH), 64, 0, sB>>>(pk, cosb, sinb, pKh, pKl, T);
    cudaEventRecord(evB, sB);

    // --- stream C: V chain (FMA pipe, frozen) + Wproj transpose ---
    sgemm_kv_kernel<<<dim3(512 / 32, T / 32), blk, 0, sC>>>(x, Wv, pv, T, 512, 2048);
    quant_v_kernel<<<dim3(T, N_KVH), 64, 0, sC>>>(pv, pVh, pVl, T);
    transpose_split_kernel<<<dim3(2048 / 32, 2048 / 32), blk, 0, sC>>>(
        Wproj, pwph, pwpl, 2048, 2048);
    cudaEventRecord(evC, sC);

    // --- join, then attention + output projection ---
    cudaStreamWaitEvent(s0, evA, 0);
    cudaStreamWaitEvent(s0, evB, 0);
    cudaStreamWaitEvent(s0, evC, 0);

    attn_tc_kernel<<<dim3(T / 64, N_HEAD), 128, ATT_SMEM, s0>>>(
        pQh, pQl, pKh, pKl, pVh, pVl, pyh, pyl, T);

    gemm_bf16x3_kernel<<<dim3(2048 / 128, T / 128), blk, GEMM_SMEM, s0>>>(
        pyh, pyl, pwph, pwpl, out, T, 2048, 2048);

    cudaEventDestroy(evRoot);
    cudaEventDestroy(evA);
    cudaEventDestroy(evB);
    cudaEventDestroy(evC);
    cudaStreamDestroy(sA);
    cudaStreamDestroy(sB);
    cudaStreamDestroy(sC);
}